// round 1
// baseline (speedup 1.0000x reference)
#include <cuda_runtime.h>
#include <math.h>

#define NROWS 32768          // B*L
#define HDIM  256
#define LSEQ  512
#define NBATCH 64
#define HEADD 64
#define ITEMPAD 49999

// ---------------- scratch (device globals; no allocs allowed) ----------------
__device__ float g_seqs[NROWS * HDIM];
__device__ float g_time[NROWS * HDIM];
__device__ float g_st  [NROWS * HDIM];
__device__ float g_Q   [NROWS * HDIM];
__device__ float g_q   [NROWS * HDIM];
__device__ float g_k   [NROWS * HDIM];
__device__ float g_v   [NROWS * HDIM];
__device__ float g_ao  [NROWS * HDIM];
__device__ float g_x   [NROWS * HDIM];
__device__ float g_h   [NROWS * HDIM];
__device__ float g_keep[NROWS];
__device__ float g_gates[NROWS * 2];

// ---------------- prep: pe gather, seqs/time, keep, gates --------------------
__global__ __launch_bounds__(256) void prep_kernel(
    const int* __restrict__ seqs_data, const float* __restrict__ seqs_in,
    const int* __restrict__ position, const float* __restrict__ time_in,
    const float* __restrict__ pos_table, const float* __restrict__ gate_W,
    const float* __restrict__ gate_b)
{
    const int n = blockIdx.x;
    const int h = threadIdx.x;
    const size_t idx = (size_t)n * HDIM + h;
    const int p = position[n];
    const float pe = pos_table[(size_t)p * HDIM + h];
    const float t = time_in[idx] + pe;
    const float keep = (seqs_data[n] != ITEMPAD) ? 1.f : 0.f;
    g_seqs[idx] = (seqs_in[idx] + pe) * keep;
    g_time[idx] = t;
    if (h == 0) g_keep[n] = keep;

    // gates[n][i] = sigmoid(dot(time_row, gate_W[i]) + gate_b[i])
    __shared__ float red[2][8];
    float p0 = t * gate_W[h];
    float p1 = t * gate_W[HDIM + h];
    #pragma unroll
    for (int o = 16; o; o >>= 1) {
        p0 += __shfl_xor_sync(0xffffffffu, p0, o);
        p1 += __shfl_xor_sync(0xffffffffu, p1, o);
    }
    if ((h & 31) == 0) { red[0][h >> 5] = p0; red[1][h >> 5] = p1; }
    __syncthreads();
    if (h < 2) {
        float s = 0.f;
        #pragma unroll
        for (int j = 0; j < 8; j++) s += red[h][j];
        g_gates[(size_t)n * 2 + h] = 1.f / (1.f + __expf(-(s + gate_b[h])));
    }
}

// ---------------- layernorm (optionally fused residual add) ------------------
template<bool ADD>
__global__ __launch_bounds__(256) void ln_kernel(
    const float* __restrict__ A, const float* __restrict__ B2,
    const float* __restrict__ g, const float* __restrict__ beta,
    float* __restrict__ dst)
{
    const int n = blockIdx.x;
    const int h = threadIdx.x;
    const size_t idx = (size_t)n * HDIM + h;
    float x = A[idx];
    if (ADD) x += B2[idx];
    float s = x, q = x * x;
    __shared__ float rs[8], rq[8];
    #pragma unroll
    for (int o = 16; o; o >>= 1) {
        s += __shfl_xor_sync(0xffffffffu, s, o);
        q += __shfl_xor_sync(0xffffffffu, q, o);
    }
    if ((h & 31) == 0) { rs[h >> 5] = s; rq[h >> 5] = q; }
    __syncthreads();
    float tot = 0.f, totq = 0.f;
    #pragma unroll
    for (int j = 0; j < 8; j++) { tot += rs[j]; totq += rq[j]; }
    const float mean = tot * (1.f / HDIM);
    const float var  = totq * (1.f / HDIM) - mean * mean;
    dst[idx] = (x - mean) * rsqrtf(var + 1e-8f) * g[h] + beta[h];
}

// ---------------- elementwise add (st = seqs + time) -------------------------
__global__ __launch_bounds__(256) void add_kernel(
    const float4* __restrict__ a, const float4* __restrict__ b, float4* __restrict__ c)
{
    const int total = NROWS * HDIM / 4;
    for (int i = blockIdx.x * blockDim.x + threadIdx.x; i < total;
         i += gridDim.x * blockDim.x) {
        float4 x = a[i], y = b[i];
        x.x += y.x; x.y += y.y; x.z += y.z; x.w += y.w;
        c[i] = x;
    }
}

// ---------------- GEMM: C[M,256] = A[M,256] @ W[256,256]^T + bias ------------
// EPI: 0 = plain, 1 = relu, 2 = (+R, *keep[row])
template<int EPI>
__global__ __launch_bounds__(256) void gemm_kernel(
    const float* __restrict__ A, const float* __restrict__ W,
    const float* __restrict__ bias, const float* __restrict__ R,
    float* __restrict__ C)
{
    __shared__ float As[16][64];
    __shared__ float Bs[16][64];
    const int t = threadIdx.x;
    const int bm = blockIdx.x << 6;
    const int bn = blockIdx.y << 6;
    const int tm = (t >> 4) << 2;
    const int tn = (t & 15) << 2;
    const int lr = t >> 2;
    const int lk = (t & 3) << 2;
    float acc[4][4] = {};

    const float4* Ap = (const float4*)(A + (size_t)(bm + lr) * HDIM + lk);
    const float4* Wp = (const float4*)(W + (size_t)(bn + lr) * HDIM + lk);

    for (int k0 = 0; k0 < HDIM; k0 += 16) {
        float4 av = Ap[k0 >> 2];
        float4 bv = Wp[k0 >> 2];
        As[lk + 0][lr] = av.x; As[lk + 1][lr] = av.y;
        As[lk + 2][lr] = av.z; As[lk + 3][lr] = av.w;
        Bs[lk + 0][lr] = bv.x; Bs[lk + 1][lr] = bv.y;
        Bs[lk + 2][lr] = bv.z; Bs[lk + 3][lr] = bv.w;
        __syncthreads();
        #pragma unroll
        for (int kk = 0; kk < 16; kk++) {
            float4 a = *(const float4*)&As[kk][tm];
            float4 b = *(const float4*)&Bs[kk][tn];
            acc[0][0] += a.x*b.x; acc[0][1] += a.x*b.y; acc[0][2] += a.x*b.z; acc[0][3] += a.x*b.w;
            acc[1][0] += a.y*b.x; acc[1][1] += a.y*b.y; acc[1][2] += a.y*b.z; acc[1][3] += a.y*b.w;
            acc[2][0] += a.z*b.x; acc[2][1] += a.z*b.y; acc[2][2] += a.z*b.z; acc[2][3] += a.z*b.w;
            acc[3][0] += a.w*b.x; acc[3][1] += a.w*b.y; acc[3][2] += a.w*b.z; acc[3][3] += a.w*b.w;
        }
        __syncthreads();
    }

    const float4 bcol = *(const float4*)(bias + bn + tn);
    #pragma unroll
    for (int i = 0; i < 4; i++) {
        const int row = bm + tm + i;
        float4 v;
        v.x = acc[i][0] + bcol.x; v.y = acc[i][1] + bcol.y;
        v.z = acc[i][2] + bcol.z; v.w = acc[i][3] + bcol.w;
        if (EPI == 1) {
            v.x = fmaxf(v.x, 0.f); v.y = fmaxf(v.y, 0.f);
            v.z = fmaxf(v.z, 0.f); v.w = fmaxf(v.w, 0.f);
        }
        if (EPI == 2) {
            const float keep = g_keep[row];
            const float4 r = *(const float4*)(R + (size_t)row * HDIM + bn + tn);
            v.x = (v.x + r.x) * keep; v.y = (v.y + r.y) * keep;
            v.z = (v.z + r.z) * keep; v.w = (v.w + r.w) * keep;
        }
        *(float4*)(C + (size_t)row * HDIM + bn + tn) = v;
    }
}

// ---------------- flash attention (causal, gated) ----------------------------
// grid (L/128, NH, B), 256 threads. 2 threads per q row, 32 d-components each.
__global__ __launch_bounds__(256) void attn_kernel(int blk)
{
    __shared__ float Ks[64][64];
    __shared__ float Vs[64][64];
    __shared__ float tgk[64];
    const int t = threadIdx.x;
    const int row = t >> 1;
    const int d0 = (t & 1) << 5;
    const int qt = blockIdx.x, hh = blockIdx.y, b = blockIdx.z;
    const int qg = qt * 128 + row;
    const size_t nq = (size_t)b * LSEQ + qg;

    float qreg[32];
    {
        const float4* qp = (const float4*)(g_q + nq * HDIM + hh * HEADD + d0);
        #pragma unroll
        for (int j = 0; j < 8; j++) {
            float4 v = qp[j];
            qreg[4*j] = v.x; qreg[4*j+1] = v.y; qreg[4*j+2] = v.z; qreg[4*j+3] = v.w;
        }
    }
    const float cq = 0.125f * g_gates[nq * 2 + blk];   // scale * tg[q]
    float m = -1e30f, l = 0.f;
    float O[32];
    #pragma unroll
    for (int j = 0; j < 32; j++) O[j] = 0.f;

    const int qgw = qt * 128 + ((t >> 5) << 4) + 15;   // warp-max q row
    const int nkt = (qt + 1) * 2;
    const int lr = t >> 2, lc = (t & 3) << 4;

    for (int kt = 0; kt < nkt; kt++) {
        const size_t nk = (size_t)b * LSEQ + kt * 64 + lr;
        const float4* kp = (const float4*)(g_k + nk * HDIM + hh * HEADD + lc);
        const float4* vp = (const float4*)(g_v + nk * HDIM + hh * HEADD + lc);
        #pragma unroll
        for (int j = 0; j < 4; j++) {
            *(float4*)&Ks[lr][lc + 4*j] = kp[j];
            *(float4*)&Vs[lr][lc + 4*j] = vp[j];
        }
        if (t < 64) tgk[t] = g_gates[((size_t)b * LSEQ + kt * 64 + t) * 2 + blk];
        __syncthreads();

        int klim = qgw - kt * 64 + 1;
        if (klim > 64) klim = 64;
        for (int k = 0; k < klim; k++) {
            float part = 0.f;
            #pragma unroll
            for (int j = 0; j < 8; j++) {
                float4 kv = *(const float4*)&Ks[k][d0 + 4*j];
                part += qreg[4*j]*kv.x + qreg[4*j+1]*kv.y + qreg[4*j+2]*kv.z + qreg[4*j+3]*kv.w;
            }
            part += __shfl_xor_sync(0xffffffffu, part, 1);
            if (kt * 64 + k <= qg) {
                const float s = part * cq * tgk[k];
                const float mn = fmaxf(m, s);
                const float p = __expf(s - mn);
                if (mn > m) {
                    const float corr = __expf(m - mn);
                    l *= corr;
                    #pragma unroll
                    for (int j = 0; j < 32; j++) O[j] *= corr;
                    m = mn;
                }
                l += p;
                #pragma unroll
                for (int j = 0; j < 8; j++) {
                    float4 vv = *(const float4*)&Vs[k][d0 + 4*j];
                    O[4*j]   += p * vv.x; O[4*j+1] += p * vv.y;
                    O[4*j+2] += p * vv.z; O[4*j+3] += p * vv.w;
                }
            }
        }
        __syncthreads();
    }

    const float inv = 1.f / l;
    float4* op = (float4*)(g_ao + nq * HDIM + hh * HEADD + d0);
    #pragma unroll
    for (int j = 0; j < 8; j++) {
        float4 v;
        v.x = O[4*j] * inv; v.y = O[4*j+1] * inv;
        v.z = O[4*j+2] * inv; v.w = O[4*j+3] * inv;
        op[j] = v;
    }
}

// ---------------- launcher ---------------------------------------------------
extern "C" void kernel_launch(void* const* d_in, const int* in_sizes, int n_in,
                              void* d_out, int out_size)
{
    const int*   seqs_data = (const int*)  d_in[0];
    const float* seqs_in   = (const float*)d_in[1];
    const int*   position  = (const int*)  d_in[2];
    const float* time_in   = (const float*)d_in[3];
    const float* pos_table = (const float*)d_in[4];
    const float* gate_W    = (const float*)d_in[5];
    const float* gate_b    = (const float*)d_in[6];
    const float* ln_attn_g = (const float*)d_in[7];
    const float* ln_attn_b = (const float*)d_in[8];
    const float* qW        = (const float*)d_in[9];
    const float* qb        = (const float*)d_in[10];
    const float* kW        = (const float*)d_in[11];
    const float* kb        = (const float*)d_in[12];
    const float* vW        = (const float*)d_in[13];
    const float* vb        = (const float*)d_in[14];
    const float* ln_ffn_g  = (const float*)d_in[15];
    const float* ln_ffn_b  = (const float*)d_in[16];
    const float* c1W       = (const float*)d_in[17];
    const float* c1b       = (const float*)d_in[18];
    const float* c2W       = (const float*)d_in[19];
    const float* c2b       = (const float*)d_in[20];
    const float* last_g    = (const float*)d_in[21];
    const float* last_b    = (const float*)d_in[22];

    float *p_seqs, *p_time, *p_st, *p_Q, *p_q, *p_k, *p_v, *p_ao, *p_x, *p_h;
    cudaGetSymbolAddress((void**)&p_seqs, g_seqs);
    cudaGetSymbolAddress((void**)&p_time, g_time);
    cudaGetSymbolAddress((void**)&p_st,   g_st);
    cudaGetSymbolAddress((void**)&p_Q,    g_Q);
    cudaGetSymbolAddress((void**)&p_q,    g_q);
    cudaGetSymbolAddress((void**)&p_k,    g_k);
    cudaGetSymbolAddress((void**)&p_v,    g_v);
    cudaGetSymbolAddress((void**)&p_ao,   g_ao);
    cudaGetSymbolAddress((void**)&p_x,    g_x);
    cudaGetSymbolAddress((void**)&p_h,    g_h);

    prep_kernel<<<NROWS, 256>>>(seqs_data, seqs_in, position, time_in,
                                pos_table, gate_W, gate_b);

    const dim3 ggrid(512, 4);
    for (int i = 0; i < 2; i++) {
        ln_kernel<false><<<NROWS, 256>>>(p_seqs, nullptr,
                                         ln_attn_g + i * HDIM, ln_attn_b + i * HDIM, p_Q);
        add_kernel<<<2048, 256>>>((const float4*)p_seqs, (const float4*)p_time,
                                  (float4*)p_st);
        gemm_kernel<0><<<ggrid, 256>>>(p_Q,    qW + (size_t)i * HDIM * HDIM, qb + i * HDIM, nullptr, p_q);
        gemm_kernel<0><<<ggrid, 256>>>(p_time, kW + (size_t)i * HDIM * HDIM, kb + i * HDIM, nullptr, p_k);
        gemm_kernel<0><<<ggrid, 256>>>(p_st,   vW + (size_t)i * HDIM * HDIM, vb + i * HDIM, nullptr, p_v);
        attn_kernel<<<dim3(4, 4, NBATCH), 256>>>(i);
        ln_kernel<true><<<NROWS, 256>>>(p_Q, p_ao,
                                        ln_ffn_g + i * HDIM, ln_ffn_b + i * HDIM, p_x);
        gemm_kernel<1><<<ggrid, 256>>>(p_x, c1W + (size_t)i * HDIM * HDIM, c1b + i * HDIM, nullptr, p_h);
        gemm_kernel<2><<<ggrid, 256>>>(p_h, c2W + (size_t)i * HDIM * HDIM, c2b + i * HDIM, p_x, p_seqs);
    }
    ln_kernel<false><<<NROWS, 256>>>(p_seqs, nullptr, last_g, last_b, (float*)d_out);
}

// round 2
// speedup vs baseline: 1.3926x; 1.3926x over previous
#include <cuda_runtime.h>
#include <math.h>

#define NROWS 32768          // B*L
#define HDIM  256
#define LSEQ  512
#define NBATCH 64
#define HEADD 64
#define ITEMPAD 49999

// ---------------- scratch (device globals; no allocs allowed) ----------------
__device__ float g_seqs[NROWS * HDIM];
__device__ float g_time[NROWS * HDIM];
__device__ float g_st  [NROWS * HDIM];
__device__ float g_Q   [NROWS * HDIM];
__device__ float g_q   [NROWS * HDIM];
__device__ float g_k   [NROWS * HDIM];
__device__ float g_v   [NROWS * HDIM];
__device__ float g_ao  [NROWS * HDIM];
__device__ float g_x   [NROWS * HDIM];
__device__ float g_h   [NROWS * HDIM];
__device__ float g_keep[NROWS];
__device__ float g_gates[NROWS * 2];

// ---------------- packed f32x2 helpers (sm_103a FFMA2) -----------------------
typedef unsigned long long u64;

__device__ __forceinline__ u64 pack2(float lo, float hi) {
    u64 r;
    asm("mov.b64 %0, {%1, %2};" : "=l"(r) : "f"(lo), "f"(hi));
    return r;
}
__device__ __forceinline__ u64 dup2(float x) {
    u64 r;
    asm("mov.b64 %0, {%1, %1};" : "=l"(r) : "f"(x));
    return r;
}
__device__ __forceinline__ void fma2(u64& acc, u64 a, u64 b) {
    asm("fma.rn.f32x2 %0, %1, %2, %0;" : "+l"(acc) : "l"(a), "l"(b));
}
__device__ __forceinline__ void mul2(u64& d, u64 a) {
    asm("mul.rn.f32x2 %0, %0, %1;" : "+l"(d) : "l"(a));
}
__device__ __forceinline__ float2 unpk2(u64 v) {
    float2 r;
    asm("mov.b64 {%0, %1}, %2;" : "=f"(r.x), "=f"(r.y) : "l"(v));
    return r;
}

// ---------------- prep: pe gather, seqs/time, keep, gates --------------------
__global__ __launch_bounds__(256) void prep_kernel(
    const int* __restrict__ seqs_data, const float* __restrict__ seqs_in,
    const int* __restrict__ position, const float* __restrict__ time_in,
    const float* __restrict__ pos_table, const float* __restrict__ gate_W,
    const float* __restrict__ gate_b)
{
    const int n = blockIdx.x;
    const int h = threadIdx.x;
    const size_t idx = (size_t)n * HDIM + h;
    const int p = position[n];
    const float pe = pos_table[(size_t)p * HDIM + h];
    const float t = time_in[idx] + pe;
    const float keep = (seqs_data[n] != ITEMPAD) ? 1.f : 0.f;
    g_seqs[idx] = (seqs_in[idx] + pe) * keep;
    g_time[idx] = t;
    if (h == 0) g_keep[n] = keep;

    __shared__ float red[2][8];
    float p0 = t * gate_W[h];
    float p1 = t * gate_W[HDIM + h];
    #pragma unroll
    for (int o = 16; o; o >>= 1) {
        p0 += __shfl_xor_sync(0xffffffffu, p0, o);
        p1 += __shfl_xor_sync(0xffffffffu, p1, o);
    }
    if ((h & 31) == 0) { red[0][h >> 5] = p0; red[1][h >> 5] = p1; }
    __syncthreads();
    if (h < 2) {
        float s = 0.f;
        #pragma unroll
        for (int j = 0; j < 8; j++) s += red[h][j];
        g_gates[(size_t)n * 2 + h] = 1.f / (1.f + __expf(-(s + gate_b[h])));
    }
}

// ---------------- layernorm (optionally fused residual add) ------------------
template<bool ADD>
__global__ __launch_bounds__(256) void ln_kernel(
    const float* __restrict__ A, const float* __restrict__ B2,
    const float* __restrict__ g, const float* __restrict__ beta,
    float* __restrict__ dst)
{
    const int n = blockIdx.x;
    const int h = threadIdx.x;
    const size_t idx = (size_t)n * HDIM + h;
    float x = A[idx];
    if (ADD) x += B2[idx];
    float s = x, q = x * x;
    __shared__ float rs[8], rq[8];
    #pragma unroll
    for (int o = 16; o; o >>= 1) {
        s += __shfl_xor_sync(0xffffffffu, s, o);
        q += __shfl_xor_sync(0xffffffffu, q, o);
    }
    if ((h & 31) == 0) { rs[h >> 5] = s; rq[h >> 5] = q; }
    __syncthreads();
    float tot = 0.f, totq = 0.f;
    #pragma unroll
    for (int j = 0; j < 8; j++) { tot += rs[j]; totq += rq[j]; }
    const float mean = tot * (1.f / HDIM);
    const float var  = totq * (1.f / HDIM) - mean * mean;
    dst[idx] = (x - mean) * rsqrtf(var + 1e-8f) * g[h] + beta[h];
}

// ---------------- elementwise add (st = seqs + time) -------------------------
__global__ __launch_bounds__(256) void add_kernel(
    const float4* __restrict__ a, const float4* __restrict__ b, float4* __restrict__ c)
{
    const int total = NROWS * HDIM / 4;
    for (int i = blockIdx.x * blockDim.x + threadIdx.x; i < total;
         i += gridDim.x * blockDim.x) {
        float4 x = a[i], y = b[i];
        x.x += y.x; x.y += y.y; x.z += y.z; x.w += y.w;
        c[i] = x;
    }
}

// ---------------- GEMM v2: C[M,256] = A @ W^T + bias (128x128 tile, FFMA2) ---
// EPI: 0 = plain, 1 = relu, 2 = (+R, *keep[row])
template<int EPI>
__global__ __launch_bounds__(256) void gemm_kernel(
    const float* __restrict__ A, const float* __restrict__ W,
    const float* __restrict__ bias, const float* __restrict__ R,
    float* __restrict__ C)
{
    __shared__ __align__(16) float As[16][132];
    __shared__ __align__(16) float Bs[16][132];
    const int t  = threadIdx.x;
    const int tx = t & 15, ty = t >> 4;
    const int bm = blockIdx.x << 7, bn = blockIdx.y << 7;
    const int lr = t >> 1, lc = (t & 1) << 3;

    u64 acc[8][4];
    #pragma unroll
    for (int i = 0; i < 8; i++)
        #pragma unroll
        for (int j = 0; j < 4; j++) acc[i][j] = 0ull;

    const float* Ap = A + (size_t)(bm + lr) * HDIM + lc;
    const float* Wp = W + (size_t)(bn + lr) * HDIM + lc;

    for (int k0 = 0; k0 < HDIM; k0 += 16) {
        float4 a0 = *(const float4*)(Ap + k0);
        float4 a1 = *(const float4*)(Ap + k0 + 4);
        float4 w0 = *(const float4*)(Wp + k0);
        float4 w1 = *(const float4*)(Wp + k0 + 4);
        As[lc+0][lr] = a0.x; As[lc+1][lr] = a0.y; As[lc+2][lr] = a0.z; As[lc+3][lr] = a0.w;
        As[lc+4][lr] = a1.x; As[lc+5][lr] = a1.y; As[lc+6][lr] = a1.z; As[lc+7][lr] = a1.w;
        Bs[lc+0][lr] = w0.x; Bs[lc+1][lr] = w0.y; Bs[lc+2][lr] = w0.z; Bs[lc+3][lr] = w0.w;
        Bs[lc+4][lr] = w1.x; Bs[lc+5][lr] = w1.y; Bs[lc+6][lr] = w1.z; Bs[lc+7][lr] = w1.w;
        __syncthreads();
        #pragma unroll
        for (int kk = 0; kk < 16; kk++) {
            float a[8];
            *(float4*)(a)     = *(const float4*)&As[kk][ty * 8];
            *(float4*)(a + 4) = *(const float4*)&As[kk][ty * 8 + 4];
            ulonglong2 b01 = *(const ulonglong2*)&Bs[kk][tx * 8];
            ulonglong2 b23 = *(const ulonglong2*)&Bs[kk][tx * 8 + 4];
            #pragma unroll
            for (int i = 0; i < 8; i++) {
                u64 ad = dup2(a[i]);
                fma2(acc[i][0], ad, b01.x);
                fma2(acc[i][1], ad, b01.y);
                fma2(acc[i][2], ad, b23.x);
                fma2(acc[i][3], ad, b23.y);
            }
        }
        __syncthreads();
    }

    float bb[8];
    *(float4*)(bb)     = *(const float4*)(bias + bn + tx * 8);
    *(float4*)(bb + 4) = *(const float4*)(bias + bn + tx * 8 + 4);

    #pragma unroll
    for (int i = 0; i < 8; i++) {
        const int row = bm + ty * 8 + i;
        float v[8];
        float2 p0 = unpk2(acc[i][0]), p1 = unpk2(acc[i][1]);
        float2 p2 = unpk2(acc[i][2]), p3 = unpk2(acc[i][3]);
        v[0]=p0.x+bb[0]; v[1]=p0.y+bb[1]; v[2]=p1.x+bb[2]; v[3]=p1.y+bb[3];
        v[4]=p2.x+bb[4]; v[5]=p2.y+bb[5]; v[6]=p3.x+bb[6]; v[7]=p3.y+bb[7];
        if (EPI == 1) {
            #pragma unroll
            for (int j = 0; j < 8; j++) v[j] = fmaxf(v[j], 0.f);
        }
        if (EPI == 2) {
            const float keep = g_keep[row];
            const float4 r0 = *(const float4*)(R + (size_t)row * HDIM + bn + tx * 8);
            const float4 r1 = *(const float4*)(R + (size_t)row * HDIM + bn + tx * 8 + 4);
            v[0]=(v[0]+r0.x)*keep; v[1]=(v[1]+r0.y)*keep; v[2]=(v[2]+r0.z)*keep; v[3]=(v[3]+r0.w)*keep;
            v[4]=(v[4]+r1.x)*keep; v[5]=(v[5]+r1.y)*keep; v[6]=(v[6]+r1.z)*keep; v[7]=(v[7]+r1.w)*keep;
        }
        *(float4*)(C + (size_t)row * HDIM + bn + tx * 8)     = *(float4*)(v);
        *(float4*)(C + (size_t)row * HDIM + bn + tx * 8 + 4) = *(float4*)(v + 4);
    }
}

// ---------------- flash attention v2 (tiled, causal, gated) ------------------
// grid (4, NH, B), 256 threads. Block = 128 q rows, full head (hd=64).
// K tiles of 64. Thread (ty,tx): owns 8 q-rows (ty*8..), 4 k-cols / 4 d-cols (tx*4..).
#define QS_STRIDE 132   // QsT[d][q]
#define KS_STRIDE 65    // KsT[d][k]
#define VS_STRIDE 68    // Vs[k][d]
#define PS_STRIDE 68    // Ps[q][k]
#define QS_FLOATS (64 * QS_STRIDE)
#define KS_FLOATS (64 * KS_STRIDE)
#define VS_FLOATS (64 * VS_STRIDE)
#define PS_FLOATS (128 * PS_STRIDE)
#define ATTN_SMEM ((QS_FLOATS + KS_FLOATS + VS_FLOATS + PS_FLOATS) * 4)

__global__ __launch_bounds__(256) void attn_kernel(int blk)
{
    extern __shared__ __align__(16) float sm[];
    float* QsT = sm;
    float* KsT = QsT + QS_FLOATS;
    float* Vs  = KsT + KS_FLOATS;
    float* Ps  = Vs  + VS_FLOATS;

    const int t  = threadIdx.x;
    const int tx = t & 15, ty = t >> 4;
    const int qt = blockIdx.x, hh = blockIdx.y, b = blockIdx.z;
    const int q0 = qt * 128;
    const size_t browbase = (size_t)b * LSEQ;

    // Load Q tile transposed into QsT[d][q]
    {
        const int tok = t >> 1;
        const int d32 = (t & 1) << 5;
        const float* qp = g_q + (browbase + q0 + tok) * HDIM + hh * HEADD + d32;
        #pragma unroll
        for (int jj = 0; jj < 8; jj++) {
            float4 v = *(const float4*)(qp + 4 * jj);
            const int d = d32 + 4 * jj;
            QsT[(d + 0) * QS_STRIDE + tok] = v.x;
            QsT[(d + 1) * QS_STRIDE + tok] = v.y;
            QsT[(d + 2) * QS_STRIDE + tok] = v.z;
            QsT[(d + 3) * QS_STRIDE + tok] = v.w;
        }
    }

    float cq[8], mrow[8], lrow[8];
    u64 O[8][2];
    #pragma unroll
    for (int i = 0; i < 8; i++) {
        cq[i]  = 0.125f * g_gates[(browbase + q0 + ty * 8 + i) * 2 + blk];
        mrow[i] = -1e30f; lrow[i] = 0.f;
        O[i][0] = 0ull; O[i][1] = 0ull;
    }
    __syncthreads();

    const int nkt = 2 * (qt + 1);
    for (int kt = 0; kt < nkt; kt++) {
        const int k0 = kt * 64;
        const bool need_mask = (k0 + 63 > q0);  // last two tiles

        // Load K tile transposed, V tile natural
        {
            const int tok = t >> 2;
            const int d16 = (t & 3) << 4;
            const float* kp = g_k + (browbase + k0 + tok) * HDIM + hh * HEADD + d16;
            const float* vp = g_v + (browbase + k0 + tok) * HDIM + hh * HEADD + d16;
            #pragma unroll
            for (int jj = 0; jj < 4; jj++) {
                float4 kv = *(const float4*)(kp + 4 * jj);
                const int d = d16 + 4 * jj;
                KsT[(d + 0) * KS_STRIDE + tok] = kv.x;
                KsT[(d + 1) * KS_STRIDE + tok] = kv.y;
                KsT[(d + 2) * KS_STRIDE + tok] = kv.z;
                KsT[(d + 3) * KS_STRIDE + tok] = kv.w;
                *(float4*)&Vs[tok * VS_STRIDE + d] = *(const float4*)(vp + 4 * jj);
            }
        }
        __syncthreads();

        // ---- Phase A: S = Q K^T  (8q x 4k per thread) ----
        u64 sp[8][2];
        #pragma unroll
        for (int i = 0; i < 8; i++) { sp[i][0] = 0ull; sp[i][1] = 0ull; }
        #pragma unroll 4
        for (int kk = 0; kk < 64; kk++) {
            const float* qr = QsT + kk * QS_STRIDE + ty * 8;
            float a[8];
            *(float4*)(a)     = *(const float4*)(qr);
            *(float4*)(a + 4) = *(const float4*)(qr + 4);
            const float* kr = KsT + kk * KS_STRIDE + tx * 4;
            u64 bp0 = pack2(kr[0], kr[1]);
            u64 bp1 = pack2(kr[2], kr[3]);
            #pragma unroll
            for (int i = 0; i < 8; i++) {
                u64 ad = dup2(a[i]);
                fma2(sp[i][0], ad, bp0);
                fma2(sp[i][1], ad, bp1);
            }
        }

        // ---- softmax update ----
        float tg[4];
        #pragma unroll
        for (int j = 0; j < 4; j++)
            tg[j] = g_gates[(browbase + k0 + tx * 4 + j) * 2 + blk];

        float alpha[8];
        #pragma unroll
        for (int i = 0; i < 8; i++) {
            const int qg = q0 + ty * 8 + i;
            float2 s01 = unpk2(sp[i][0]);
            float2 s23 = unpk2(sp[i][1]);
            float s[4] = { s01.x, s01.y, s23.x, s23.y };
            #pragma unroll
            for (int j = 0; j < 4; j++) {
                float val = s[j] * cq[i] * tg[j];
                if (need_mask && (k0 + tx * 4 + j > qg)) val = -1e30f;
                s[j] = val;
            }
            float mt = fmaxf(fmaxf(s[0], s[1]), fmaxf(s[2], s[3]));
            #pragma unroll
            for (int o = 1; o <= 8; o <<= 1)
                mt = fmaxf(mt, __shfl_xor_sync(0xffffffffu, mt, o));
            const float mn = fmaxf(mrow[i], mt);
            alpha[i] = __expf(mrow[i] - mn);
            mrow[i] = mn;
            float rs = 0.f;
            float p[4];
            #pragma unroll
            for (int j = 0; j < 4; j++) {
                float pv = (s[j] > -5e29f) ? __expf(s[j] - mn) : 0.f;
                p[j] = pv; rs += pv;
            }
            #pragma unroll
            for (int o = 1; o <= 8; o <<= 1)
                rs += __shfl_xor_sync(0xffffffffu, rs, o);
            lrow[i] = lrow[i] * alpha[i] + rs;
            float* pr = Ps + (ty * 8 + i) * PS_STRIDE + tx * 4;
            pr[0] = p[0]; pr[1] = p[1]; pr[2] = p[2]; pr[3] = p[3];
        }
        __syncthreads();

        // ---- Phase B: O = O*alpha + P V  (8q x 4d per thread) ----
        #pragma unroll
        for (int i = 0; i < 8; i++) {
            u64 ad = dup2(alpha[i]);
            mul2(O[i][0], ad);
            mul2(O[i][1], ad);
        }
        #pragma unroll 4
        for (int kk = 0; kk < 64; kk++) {
            const ulonglong2 vv = *(const ulonglong2*)&Vs[kk * VS_STRIDE + tx * 4];
            #pragma unroll
            for (int i = 0; i < 8; i++) {
                u64 ad = dup2(Ps[(ty * 8 + i) * PS_STRIDE + kk]);
                fma2(O[i][0], ad, vv.x);
                fma2(O[i][1], ad, vv.y);
            }
        }
        __syncthreads();
    }

    // epilogue: normalize + store
    #pragma unroll
    for (int i = 0; i < 8; i++) {
        const float inv = 1.f / lrow[i];
        float2 o0 = unpk2(O[i][0]);
        float2 o1 = unpk2(O[i][1]);
        float4 v;
        v.x = o0.x * inv; v.y = o0.y * inv;
        v.z = o1.x * inv; v.w = o1.y * inv;
        *(float4*)(g_ao + (browbase + q0 + ty * 8 + i) * HDIM + hh * HEADD + tx * 4) = v;
    }
}

// ---------------- launcher ---------------------------------------------------
extern "C" void kernel_launch(void* const* d_in, const int* in_sizes, int n_in,
                              void* d_out, int out_size)
{
    const int*   seqs_data = (const int*)  d_in[0];
    const float* seqs_in   = (const float*)d_in[1];
    const int*   position  = (const int*)  d_in[2];
    const float* time_in   = (const float*)d_in[3];
    const float* pos_table = (const float*)d_in[4];
    const float* gate_W    = (const float*)d_in[5];
    const float* gate_b    = (const float*)d_in[6];
    const float* ln_attn_g = (const float*)d_in[7];
    const float* ln_attn_b = (const float*)d_in[8];
    const float* qW        = (const float*)d_in[9];
    const float* qb        = (const float*)d_in[10];
    const float* kW        = (const float*)d_in[11];
    const float* kb        = (const float*)d_in[12];
    const float* vW        = (const float*)d_in[13];
    const float* vb        = (const float*)d_in[14];
    const float* ln_ffn_g  = (const float*)d_in[15];
    const float* ln_ffn_b  = (const float*)d_in[16];
    const float* c1W       = (const float*)d_in[17];
    const float* c1b       = (const float*)d_in[18];
    const float* c2W       = (const float*)d_in[19];
    const float* c2b       = (const float*)d_in[20];
    const float* last_g    = (const float*)d_in[21];
    const float* last_b    = (const float*)d_in[22];

    float *p_seqs, *p_time, *p_st, *p_Q, *p_q, *p_k, *p_v, *p_ao, *p_x, *p_h;
    cudaGetSymbolAddress((void**)&p_seqs, g_seqs);
    cudaGetSymbolAddress((void**)&p_time, g_time);
    cudaGetSymbolAddress((void**)&p_st,   g_st);
    cudaGetSymbolAddress((void**)&p_Q,    g_Q);
    cudaGetSymbolAddress((void**)&p_q,    g_q);
    cudaGetSymbolAddress((void**)&p_k,    g_k);
    cudaGetSymbolAddress((void**)&p_v,    g_v);
    cudaGetSymbolAddress((void**)&p_ao,   g_ao);
    cudaGetSymbolAddress((void**)&p_x,    g_x);
    cudaGetSymbolAddress((void**)&p_h,    g_h);

    cudaFuncSetAttribute(attn_kernel, cudaFuncAttributeMaxDynamicSharedMemorySize,
                         ATTN_SMEM);

    prep_kernel<<<NROWS, 256>>>(seqs_data, seqs_in, position, time_in,
                                pos_table, gate_W, gate_b);

    const dim3 ggrid(256, 2);
    for (int i = 0; i < 2; i++) {
        ln_kernel<false><<<NROWS, 256>>>(p_seqs, nullptr,
                                         ln_attn_g + i * HDIM, ln_attn_b + i * HDIM, p_Q);
        add_kernel<<<2048, 256>>>((const float4*)p_seqs, (const float4*)p_time,
                                  (float4*)p_st);
        gemm_kernel<0><<<ggrid, 256>>>(p_Q,    qW + (size_t)i * HDIM * HDIM, qb + i * HDIM, nullptr, p_q);
        gemm_kernel<0><<<ggrid, 256>>>(p_time, kW + (size_t)i * HDIM * HDIM, kb + i * HDIM, nullptr, p_k);
        gemm_kernel<0><<<ggrid, 256>>>(p_st,   vW + (size_t)i * HDIM * HDIM, vb + i * HDIM, nullptr, p_v);
        attn_kernel<<<dim3(4, 4, NBATCH), 256, ATTN_SMEM>>>(i);
        ln_kernel<true><<<NROWS, 256>>>(p_Q, p_ao,
                                        ln_ffn_g + i * HDIM, ln_ffn_b + i * HDIM, p_x);
        gemm_kernel<1><<<ggrid, 256>>>(p_x, c1W + (size_t)i * HDIM * HDIM, c1b + i * HDIM, nullptr, p_h);
        gemm_kernel<2><<<ggrid, 256>>>(p_h, c2W + (size_t)i * HDIM * HDIM, c2b + i * HDIM, p_x, p_seqs);
    }
    ln_kernel<false><<<NROWS, 256>>>(p_seqs, nullptr, last_g, last_b, (float*)d_out);
}

// round 4
// speedup vs baseline: 2.0789x; 1.4928x over previous
#include <cuda_runtime.h>
#include <cuda_bf16.h>
#include <math.h>

#define NROWS 32768          // B*L
#define HDIM  256
#define LSEQ  512
#define NBATCH 64
#define HEADD 64
#define ITEMPAD 49999

typedef unsigned long long u64;

// ---------------- scratch (device globals; no allocs allowed) ----------------
__device__ __align__(16) float g_seqs[NROWS * HDIM];
__device__ __align__(16) float g_time[NROWS * HDIM];
__device__ __align__(16) float g_Q   [NROWS * HDIM];
__device__ __align__(16) float g_q   [NROWS * HDIM];
__device__ __align__(16) float g_k   [NROWS * HDIM];
__device__ __align__(16) float g_v   [NROWS * HDIM];
__device__ __align__(16) float g_ao  [NROWS * HDIM];
__device__ __align__(16) float g_x   [NROWS * HDIM];
__device__ float g_keep[NROWS];
__device__ float g_gates[NROWS * 2];

// bf16 hi/lo split buffers
__device__ __align__(16) __nv_bfloat16 g_t_hi[NROWS * HDIM];
__device__ __align__(16) __nv_bfloat16 g_t_lo[NROWS * HDIM];
__device__ __align__(16) __nv_bfloat16 g_a_hi[NROWS * HDIM];   // bufA
__device__ __align__(16) __nv_bfloat16 g_a_lo[NROWS * HDIM];
__device__ __align__(16) __nv_bfloat16 g_b_hi[NROWS * HDIM];   // bufB
__device__ __align__(16) __nv_bfloat16 g_b_lo[NROWS * HDIM];
// weights: [mat(q,k,v,c1,c2)][block][256][256]
__device__ __align__(16) __nv_bfloat16 g_w_hi[5 * 2 * HDIM * HDIM];
__device__ __align__(16) __nv_bfloat16 g_w_lo[5 * 2 * HDIM * HDIM];

// ---------------- small helpers ----------------------------------------------
__device__ __forceinline__ void split_bf(float x, __nv_bfloat16& h, __nv_bfloat16& l) {
    h = __float2bfloat16_rn(x);
    l = __float2bfloat16_rn(x - __bfloat162float(h));
}
__device__ __forceinline__ unsigned pack_bf2(__nv_bfloat16 a, __nv_bfloat16 b) {
    return (unsigned)__bfloat16_as_ushort(a) | ((unsigned)__bfloat16_as_ushort(b) << 16);
}
__device__ __forceinline__ unsigned smem_u32(const void* p) {
    unsigned a;
    asm("{ .reg .u64 t; cvta.to.shared.u64 t, %1; cvt.u32.u64 %0, t; }" : "=r"(a) : "l"(p));
    return a;
}

// packed f32x2 helpers (attention)
__device__ __forceinline__ u64 pack2(float lo, float hi) {
    u64 r; asm("mov.b64 %0, {%1, %2};" : "=l"(r) : "f"(lo), "f"(hi)); return r;
}
__device__ __forceinline__ u64 dup2(float x) {
    u64 r; asm("mov.b64 %0, {%1, %1};" : "=l"(r) : "f"(x)); return r;
}
__device__ __forceinline__ void fma2(u64& acc, u64 a, u64 b) {
    asm("fma.rn.f32x2 %0, %1, %2, %0;" : "+l"(acc) : "l"(a), "l"(b));
}
__device__ __forceinline__ void mul2(u64& d, u64 a) {
    asm("mul.rn.f32x2 %0, %0, %1;" : "+l"(d) : "l"(a));
}
__device__ __forceinline__ float2 unpk2(u64 v) {
    float2 r; asm("mov.b64 {%0, %1}, %2;" : "=f"(r.x), "=f"(r.y) : "l"(v)); return r;
}

// ---------------- warp-MMA helpers (portable: sm_80+) -------------------------
__device__ __forceinline__ void ldsm_x4(unsigned& r0, unsigned& r1, unsigned& r2,
                                        unsigned& r3, unsigned addr) {
    asm volatile("ldmatrix.sync.aligned.m8n8.x4.shared.b16 {%0,%1,%2,%3}, [%4];"
        : "=r"(r0), "=r"(r1), "=r"(r2), "=r"(r3) : "r"(addr));
}
__device__ __forceinline__ void mma16816(float* d, const unsigned* a, const unsigned* b) {
    asm volatile("mma.sync.aligned.m16n8k16.row.col.f32.bf16.bf16.f32 "
        "{%0,%1,%2,%3}, {%4,%5,%6,%7}, {%8,%9}, {%0,%1,%2,%3};"
        : "+f"(d[0]), "+f"(d[1]), "+f"(d[2]), "+f"(d[3])
        : "r"(a[0]), "r"(a[1]), "r"(a[2]), "r"(a[3]), "r"(b[0]), "r"(b[1]));
}

// ---------------- prep: pe gather, seqs/time, keep, gates, time hi/lo --------
__global__ __launch_bounds__(256) void prep_kernel(
    const int* __restrict__ seqs_data, const float* __restrict__ seqs_in,
    const int* __restrict__ position, const float* __restrict__ time_in,
    const float* __restrict__ pos_table, const float* __restrict__ gate_W,
    const float* __restrict__ gate_b)
{
    const int n = blockIdx.x;
    const int h = threadIdx.x;
    const size_t idx = (size_t)n * HDIM + h;
    const int p = position[n];
    const float pe = pos_table[(size_t)p * HDIM + h];
    const float t = time_in[idx] + pe;
    const float keep = (seqs_data[n] != ITEMPAD) ? 1.f : 0.f;
    g_seqs[idx] = (seqs_in[idx] + pe) * keep;
    g_time[idx] = t;
    __nv_bfloat16 th, tl;
    split_bf(t, th, tl);
    g_t_hi[idx] = th; g_t_lo[idx] = tl;
    if (h == 0) g_keep[n] = keep;

    __shared__ float red[2][8];
    float p0 = t * gate_W[h];
    float p1 = t * gate_W[HDIM + h];
    #pragma unroll
    for (int o = 16; o; o >>= 1) {
        p0 += __shfl_xor_sync(0xffffffffu, p0, o);
        p1 += __shfl_xor_sync(0xffffffffu, p1, o);
    }
    if ((h & 31) == 0) { red[0][h >> 5] = p0; red[1][h >> 5] = p1; }
    __syncthreads();
    if (h < 2) {
        float s = 0.f;
        #pragma unroll
        for (int j = 0; j < 8; j++) s += red[h][j];
        g_gates[(size_t)n * 2 + h] = 1.f / (1.f + __expf(-(s + gate_b[h])));
    }
}

// ---------------- weight conversion ------------------------------------------
__global__ __launch_bounds__(256) void wconv_kernel(
    const float* __restrict__ q, const float* __restrict__ k,
    const float* __restrict__ v, const float* __restrict__ c1,
    const float* __restrict__ c2)
{
    const int i = blockIdx.x * blockDim.x + threadIdx.x;   // float4 units
    if (i >= 5 * 32768) return;
    const int mat = i >> 15, rem = i & 32767;
    const float* src = (mat == 0) ? q : (mat == 1) ? k : (mat == 2) ? v : (mat == 3) ? c1 : c2;
    float4 x = ((const float4*)src)[rem];
    __nv_bfloat16 h0,l0,h1,l1,h2,l2,h3,l3;
    split_bf(x.x,h0,l0); split_bf(x.y,h1,l1); split_bf(x.z,h2,l2); split_bf(x.w,h3,l3);
    const size_t o = ((size_t)mat << 17) + (size_t)rem * 4;
    *(uint2*)(g_w_hi + o) = make_uint2(pack_bf2(h0,h1), pack_bf2(h2,h3));
    *(uint2*)(g_w_lo + o) = make_uint2(pack_bf2(l0,l1), pack_bf2(l2,l3));
}

// ---------------- layernorm (+residual, +bf16 split outputs) ------------------
template<bool ADD, bool BF>
__global__ __launch_bounds__(256) void ln_kernel(
    const float* __restrict__ A, const float* __restrict__ B2,
    const float* __restrict__ g, const float* __restrict__ beta,
    float* __restrict__ dst, __nv_bfloat16* __restrict__ Dh,
    __nv_bfloat16* __restrict__ Dl)
{
    const int n = blockIdx.x;
    const int h = threadIdx.x;
    const size_t idx = (size_t)n * HDIM + h;
    float x = A[idx];
    if (ADD) x += B2[idx];
    float s = x, q = x * x;
    __shared__ float rs[8], rq[8];
    #pragma unroll
    for (int o = 16; o; o >>= 1) {
        s += __shfl_xor_sync(0xffffffffu, s, o);
        q += __shfl_xor_sync(0xffffffffu, q, o);
    }
    if ((h & 31) == 0) { rs[h >> 5] = s; rq[h >> 5] = q; }
    __syncthreads();
    float tot = 0.f, totq = 0.f;
    #pragma unroll
    for (int j = 0; j < 8; j++) { tot += rs[j]; totq += rq[j]; }
    const float mean = tot * (1.f / HDIM);
    const float var  = totq * (1.f / HDIM) - mean * mean;
    const float y = (x - mean) * rsqrtf(var + 1e-8f) * g[h] + beta[h];
    dst[idx] = y;
    if (BF) {
        __nv_bfloat16 hh, ll;
        split_bf(y, hh, ll);
        Dh[idx] = hh; Dl[idx] = ll;
    }
}

// ---------------- add (seqs+time) -> bf16 hi/lo -------------------------------
__global__ __launch_bounds__(256) void add_kernel(
    const float4* __restrict__ a, const float4* __restrict__ b,
    __nv_bfloat16* __restrict__ Ch, __nv_bfloat16* __restrict__ Cl)
{
    const int total = NROWS * HDIM / 4;
    for (int i = blockIdx.x * blockDim.x + threadIdx.x; i < total;
         i += gridDim.x * blockDim.x) {
        float4 x = a[i], y = b[i];
        float s0 = x.x + y.x, s1 = x.y + y.y, s2 = x.z + y.z, s3 = x.w + y.w;
        __nv_bfloat16 h0,l0,h1,l1,h2,l2,h3,l3;
        split_bf(s0,h0,l0); split_bf(s1,h1,l1); split_bf(s2,h2,l2); split_bf(s3,h3,l3);
        *(uint2*)(Ch + (size_t)i * 4) = make_uint2(pack_bf2(h0,h1), pack_bf2(h2,h3));
        *(uint2*)(Cl + (size_t)i * 4) = make_uint2(pack_bf2(l0,l1), pack_bf2(l2,l3));
    }
}

// ---------------- warp-MMA GEMM: C[128,64-tile] = A @ W^T + bias --------------
// grid (M/128, N/64). 256 threads = 8 warps: warp grid 4(m) x 2(n), warp tile 32x32.
// bf16-split: D = Ah*Wh + Al*Wh + Ah*Wl   (fp32 accum)
// EPI: 0 = fp32 out, 1 = relu -> bf16 hi/lo out, 2 = (+R)*keep -> fp32 out
#define ASTRIDE 72                    // bf16 elems per smem row (pad 64->72)
#define SM_AH 0
#define SM_AL (128 * ASTRIDE)
#define SM_BH (2 * 128 * ASTRIDE)
#define SM_BL (2 * 128 * ASTRIDE + 64 * ASTRIDE)
#define GEMM_SMEM ((2 * 128 * ASTRIDE + 2 * 64 * ASTRIDE) * 2)   // 55296 bytes

template<int EPI>
__global__ __launch_bounds__(256, 2) void gemm_mma(
    const __nv_bfloat16* __restrict__ Ah, const __nv_bfloat16* __restrict__ Al,
    const __nv_bfloat16* __restrict__ Wh, const __nv_bfloat16* __restrict__ Wl,
    const float* __restrict__ bias, const float* __restrict__ R,
    float* __restrict__ Cf, __nv_bfloat16* __restrict__ Ch,
    __nv_bfloat16* __restrict__ Cl)
{
    extern __shared__ __align__(16) __nv_bfloat16 smb[];
    const int tid = threadIdx.x;
    const int lane = tid & 31, wid = tid >> 5;
    const int bm = blockIdx.x << 7;
    const int bn = blockIdx.y << 6;
    const int wm = (wid >> 1) << 5;   // 0,32,64,96
    const int wn = (wid & 1) << 5;    // 0,32

    float acc[2][4][4];
    #pragma unroll
    for (int mt = 0; mt < 2; mt++)
        #pragma unroll
        for (int nt = 0; nt < 4; nt++)
            #pragma unroll
            for (int j = 0; j < 4; j++) acc[mt][nt][j] = 0.f;

    const unsigned sbase = smem_u32(smb);

    // ldmatrix source addresses (fixed per thread, +k offset per step)
    // A frag: row = wm + mt*16 + ((lane>>3)&1)*8 + (lane&7), col = k + (lane>>4)*8
    const int a_r = ((lane >> 3) & 1) * 8 + (lane & 7);
    const int a_c = (lane >> 4) * 8;
    // B frag: row = wn + nt2*16 + (lane>>4)*8 + (lane&7), col = k + ((lane>>3)&1)*8
    const int b_r = (lane >> 4) * 8 + (lane & 7);
    const int b_c = ((lane >> 3) & 1) * 8;

    for (int c = 0; c < 4; c++) {
        // ---- global -> smem (A: 128x64, B: 64x64, hi+lo) ----
        #pragma unroll
        for (int i = 0; i < 4; i++) {
            const int v = tid + 256 * i;
            const int r = v >> 3, cc = v & 7;
            const size_t go = (size_t)(bm + r) * HDIM + c * 64 + cc * 8;
            const int so = r * ASTRIDE + cc * 8;
            *(uint4*)(smb + SM_AH + so) = *(const uint4*)(Ah + go);
            *(uint4*)(smb + SM_AL + so) = *(const uint4*)(Al + go);
        }
        #pragma unroll
        for (int i = 0; i < 2; i++) {
            const int v = tid + 256 * i;
            const int r = v >> 3, cc = v & 7;
            const size_t go = (size_t)(bn + r) * HDIM + c * 64 + cc * 8;
            const int so = r * ASTRIDE + cc * 8;
            *(uint4*)(smb + SM_BH + so) = *(const uint4*)(Wh + go);
            *(uint4*)(smb + SM_BL + so) = *(const uint4*)(Wl + go);
        }
        __syncthreads();

        #pragma unroll
        for (int ks = 0; ks < 4; ks++) {
            const int k = ks * 16;
            unsigned ah[2][4], al[2][4], bh[4][2], bl[4][2];
            #pragma unroll
            for (int mt = 0; mt < 2; mt++) {
                const unsigned off =
                    ((unsigned)((wm + mt * 16 + a_r) * ASTRIDE + k + a_c)) * 2u;
                ldsm_x4(ah[mt][0], ah[mt][1], ah[mt][2], ah[mt][3],
                        sbase + SM_AH * 2 + off);
                ldsm_x4(al[mt][0], al[mt][1], al[mt][2], al[mt][3],
                        sbase + SM_AL * 2 + off);
            }
            #pragma unroll
            for (int nt2 = 0; nt2 < 2; nt2++) {
                const unsigned off =
                    ((unsigned)((wn + nt2 * 16 + b_r) * ASTRIDE + k + b_c)) * 2u;
                unsigned r0, r1, r2, r3;
                ldsm_x4(r0, r1, r2, r3, sbase + SM_BH * 2 + off);
                bh[nt2 * 2][0] = r0; bh[nt2 * 2][1] = r1;
                bh[nt2 * 2 + 1][0] = r2; bh[nt2 * 2 + 1][1] = r3;
                ldsm_x4(r0, r1, r2, r3, sbase + SM_BL * 2 + off);
                bl[nt2 * 2][0] = r0; bl[nt2 * 2][1] = r1;
                bl[nt2 * 2 + 1][0] = r2; bl[nt2 * 2 + 1][1] = r3;
            }
            #pragma unroll
            for (int mt = 0; mt < 2; mt++)
                #pragma unroll
                for (int nt = 0; nt < 4; nt++) {
                    mma16816(acc[mt][nt], ah[mt], bh[nt]);
                    mma16816(acc[mt][nt], al[mt], bh[nt]);
                    mma16816(acc[mt][nt], ah[mt], bl[nt]);
                }
        }
        __syncthreads();
    }

    // ---- epilogue ----
    const int qrow = lane >> 2;
    const int qcol = (lane & 3) * 2;
    #pragma unroll
    for (int mt = 0; mt < 2; mt++) {
        #pragma unroll
        for (int half = 0; half < 2; half++) {
            const int row = bm + wm + mt * 16 + qrow + half * 8;
            float keep = 1.f;
            if (EPI == 2) keep = g_keep[row];
            #pragma unroll
            for (int nt = 0; nt < 4; nt++) {
                const int col = bn + wn + nt * 8 + qcol;
                float v0 = acc[mt][nt][half * 2]     + __ldg(bias + col);
                float v1 = acc[mt][nt][half * 2 + 1] + __ldg(bias + col + 1);
                const size_t o = (size_t)row * HDIM + col;
                if (EPI == 0) {
                    *(float2*)(Cf + o) = make_float2(v0, v1);
                } else if (EPI == 1) {
                    v0 = fmaxf(v0, 0.f); v1 = fmaxf(v1, 0.f);
                    __nv_bfloat16 h0, l0, h1, l1;
                    split_bf(v0, h0, l0); split_bf(v1, h1, l1);
                    *(unsigned*)(Ch + o) = pack_bf2(h0, h1);
                    *(unsigned*)(Cl + o) = pack_bf2(l0, l1);
                } else {
                    const float2 rr = *(const float2*)(R + o);
                    *(float2*)(Cf + o) = make_float2((v0 + rr.x) * keep,
                                                     (v1 + rr.y) * keep);
                }
            }
        }
    }
}

// ---------------- flash attention (tiled, causal, gated) ----------------------
#define QS_STRIDE 132
#define KS_STRIDE 65
#define VS_STRIDE 68
#define PS_STRIDE 68
#define QS_FLOATS (64 * QS_STRIDE)
#define KS_FLOATS (64 * KS_STRIDE)
#define VS_FLOATS (64 * VS_STRIDE)
#define PS_FLOATS (128 * PS_STRIDE)
#define ATTN_SMEM ((QS_FLOATS + KS_FLOATS + VS_FLOATS + PS_FLOATS) * 4)

__global__ __launch_bounds__(256) void attn_kernel(int blk)
{
    extern __shared__ __align__(16) float smf[];
    float* QsT = smf;
    float* KsT = QsT + QS_FLOATS;
    float* Vs  = KsT + KS_FLOATS;
    float* Ps  = Vs  + VS_FLOATS;

    const int t  = threadIdx.x;
    const int tx = t & 15, ty = t >> 4;
    const int qt = blockIdx.x, hh = blockIdx.y, b = blockIdx.z;
    const int q0 = qt * 128;
    const size_t browbase = (size_t)b * LSEQ;

    {
        const int tok = t >> 1;
        const int d32 = (t & 1) << 5;
        const float* qp = g_q + (browbase + q0 + tok) * HDIM + hh * HEADD + d32;
        #pragma unroll
        for (int jj = 0; jj < 8; jj++) {
            float4 v = *(const float4*)(qp + 4 * jj);
            const int d = d32 + 4 * jj;
            QsT[(d + 0) * QS_STRIDE + tok] = v.x;
            QsT[(d + 1) * QS_STRIDE + tok] = v.y;
            QsT[(d + 2) * QS_STRIDE + tok] = v.z;
            QsT[(d + 3) * QS_STRIDE + tok] = v.w;
        }
    }

    float cq[8], mrow[8], lrow[8];
    u64 O[8][2];
    #pragma unroll
    for (int i = 0; i < 8; i++) {
        cq[i]  = 0.125f * g_gates[(browbase + q0 + ty * 8 + i) * 2 + blk];
        mrow[i] = -1e30f; lrow[i] = 0.f;
        O[i][0] = 0ull; O[i][1] = 0ull;
    }
    __syncthreads();

    const int nkt = 2 * (qt + 1);
    for (int kt = 0; kt < nkt; kt++) {
        const int k0 = kt * 64;
        const bool need_mask = (k0 + 63 > q0);

        {
            const int tok = t >> 2;
            const int d16 = (t & 3) << 4;
            const float* kp = g_k + (browbase + k0 + tok) * HDIM + hh * HEADD + d16;
            const float* vp = g_v + (browbase + k0 + tok) * HDIM + hh * HEADD + d16;
            #pragma unroll
            for (int jj = 0; jj < 4; jj++) {
                float4 kv = *(const float4*)(kp + 4 * jj);
                const int d = d16 + 4 * jj;
                KsT[(d + 0) * KS_STRIDE + tok] = kv.x;
                KsT[(d + 1) * KS_STRIDE + tok] = kv.y;
                KsT[(d + 2) * KS_STRIDE + tok] = kv.z;
                KsT[(d + 3) * KS_STRIDE + tok] = kv.w;
                *(float4*)&Vs[tok * VS_STRIDE + d] = *(const float4*)(vp + 4 * jj);
            }
        }
        __syncthreads();

        u64 sp[8][2];
        #pragma unroll
        for (int i = 0; i < 8; i++) { sp[i][0] = 0ull; sp[i][1] = 0ull; }
        #pragma unroll 4
        for (int kk = 0; kk < 64; kk++) {
            const float* qr = QsT + kk * QS_STRIDE + ty * 8;
            float a[8];
            *(float4*)(a)     = *(const float4*)(qr);
            *(float4*)(a + 4) = *(const float4*)(qr + 4);
            const float* kr = KsT + kk * KS_STRIDE + tx * 4;
            u64 bp0 = pack2(kr[0], kr[1]);
            u64 bp1 = pack2(kr[2], kr[3]);
            #pragma unroll
            for (int i = 0; i < 8; i++) {
                u64 ad = dup2(a[i]);
                fma2(sp[i][0], ad, bp0);
                fma2(sp[i][1], ad, bp1);
            }
        }

        float tg[4];
        #pragma unroll
        for (int j = 0; j < 4; j++)
            tg[j] = g_gates[(browbase + k0 + tx * 4 + j) * 2 + blk];

        float alpha[8];
        #pragma unroll
        for (int i = 0; i < 8; i++) {
            const int qg = q0 + ty * 8 + i;
            float2 s01 = unpk2(sp[i][0]);
            float2 s23 = unpk2(sp[i][1]);
            float s[4] = { s01.x, s01.y, s23.x, s23.y };
            #pragma unroll
            for (int j = 0; j < 4; j++) {
                float val = s[j] * cq[i] * tg[j];
                if (need_mask && (k0 + tx * 4 + j > qg)) val = -1e30f;
                s[j] = val;
            }
            float mt = fmaxf(fmaxf(s[0], s[1]), fmaxf(s[2], s[3]));
            #pragma unroll
            for (int o = 1; o <= 8; o <<= 1)
                mt = fmaxf(mt, __shfl_xor_sync(0xffffffffu, mt, o));
            const float mn = fmaxf(mrow[i], mt);
            alpha[i] = __expf(mrow[i] - mn);
            mrow[i] = mn;
            float rs = 0.f;
            float p[4];
            #pragma unroll
            for (int j = 0; j < 4; j++) {
                float pv = (s[j] > -5e29f) ? __expf(s[j] - mn) : 0.f;
                p[j] = pv; rs += pv;
            }
            #pragma unroll
            for (int o = 1; o <= 8; o <<= 1)
                rs += __shfl_xor_sync(0xffffffffu, rs, o);
            lrow[i] = lrow[i] * alpha[i] + rs;
            float* pr = Ps + (ty * 8 + i) * PS_STRIDE + tx * 4;
            pr[0] = p[0]; pr[1] = p[1]; pr[2] = p[2]; pr[3] = p[3];
        }
        __syncthreads();

        #pragma unroll
        for (int i = 0; i < 8; i++) {
            u64 ad = dup2(alpha[i]);
            mul2(O[i][0], ad);
            mul2(O[i][1], ad);
        }
        #pragma unroll 4
        for (int kk = 0; kk < 64; kk++) {
            const ulonglong2 vv = *(const ulonglong2*)&Vs[kk * VS_STRIDE + tx * 4];
            #pragma unroll
            for (int i = 0; i < 8; i++) {
                u64 ad = dup2(Ps[(ty * 8 + i) * PS_STRIDE + kk]);
                fma2(O[i][0], ad, vv.x);
                fma2(O[i][1], ad, vv.y);
            }
        }
        __syncthreads();
    }

    #pragma unroll
    for (int i = 0; i < 8; i++) {
        const float inv = 1.f / lrow[i];
        float2 o0 = unpk2(O[i][0]);
        float2 o1 = unpk2(O[i][1]);
        float4 v;
        v.x = o0.x * inv; v.y = o0.y * inv;
        v.z = o1.x * inv; v.w = o1.y * inv;
        *(float4*)(g_ao + (browbase + q0 + ty * 8 + i) * HDIM + hh * HEADD + tx * 4) = v;
    }
}

// ---------------- launcher ---------------------------------------------------
extern "C" void kernel_launch(void* const* d_in, const int* in_sizes, int n_in,
                              void* d_out, int out_size)
{
    const int*   seqs_data = (const int*)  d_in[0];
    const float* seqs_in   = (const float*)d_in[1];
    const int*   position  = (const int*)  d_in[2];
    const float* time_in   = (const float*)d_in[3];
    const float* pos_table = (const float*)d_in[4];
    const float* gate_W    = (const float*)d_in[5];
    const float* gate_b    = (const float*)d_in[6];
    const float* ln_attn_g = (const float*)d_in[7];
    const float* ln_attn_b = (const float*)d_in[8];
    const float* qW        = (const float*)d_in[9];
    const float* qb        = (const float*)d_in[10];
    const float* kW        = (const float*)d_in[11];
    const float* kb        = (const float*)d_in[12];
    const float* vW        = (const float*)d_in[13];
    const float* vb        = (const float*)d_in[14];
    const float* ln_ffn_g  = (const float*)d_in[15];
    const float* ln_ffn_b  = (const float*)d_in[16];
    const float* c1W       = (const float*)d_in[17];
    const float* c1b       = (const float*)d_in[18];
    const float* c2W       = (const float*)d_in[19];
    const float* c2b       = (const float*)d_in[20];
    const float* last_g    = (const float*)d_in[21];
    const float* last_b    = (const float*)d_in[22];

    float *p_seqs, *p_time, *p_Q, *p_q, *p_k, *p_v, *p_ao, *p_x;
    __nv_bfloat16 *p_th, *p_tl, *p_ah, *p_al, *p_bh, *p_bl, *p_wh, *p_wl;
    cudaGetSymbolAddress((void**)&p_seqs, g_seqs);
    cudaGetSymbolAddress((void**)&p_time, g_time);
    cudaGetSymbolAddress((void**)&p_Q,    g_Q);
    cudaGetSymbolAddress((void**)&p_q,    g_q);
    cudaGetSymbolAddress((void**)&p_k,    g_k);
    cudaGetSymbolAddress((void**)&p_v,    g_v);
    cudaGetSymbolAddress((void**)&p_ao,   g_ao);
    cudaGetSymbolAddress((void**)&p_x,    g_x);
    cudaGetSymbolAddress((void**)&p_th,   g_t_hi);
    cudaGetSymbolAddress((void**)&p_tl,   g_t_lo);
    cudaGetSymbolAddress((void**)&p_ah,   g_a_hi);
    cudaGetSymbolAddress((void**)&p_al,   g_a_lo);
    cudaGetSymbolAddress((void**)&p_bh,   g_b_hi);
    cudaGetSymbolAddress((void**)&p_bl,   g_b_lo);
    cudaGetSymbolAddress((void**)&p_wh,   g_w_hi);
    cudaGetSymbolAddress((void**)&p_wl,   g_w_lo);

    cudaFuncSetAttribute(attn_kernel, cudaFuncAttributeMaxDynamicSharedMemorySize, ATTN_SMEM);
    cudaFuncSetAttribute(gemm_mma<0>, cudaFuncAttributeMaxDynamicSharedMemorySize, GEMM_SMEM);
    cudaFuncSetAttribute(gemm_mma<1>, cudaFuncAttributeMaxDynamicSharedMemorySize, GEMM_SMEM);
    cudaFuncSetAttribute(gemm_mma<2>, cudaFuncAttributeMaxDynamicSharedMemorySize, GEMM_SMEM);

    prep_kernel<<<NROWS, 256>>>(seqs_data, seqs_in, position, time_in,
                                pos_table, gate_W, gate_b);
    wconv_kernel<<<640, 256>>>(qW, kW, vW, c1W, c2W);

    const size_t WSZ = (size_t)HDIM * HDIM;          // per (mat, block)
    const dim3 ggrid(NROWS / 128, HDIM / 64);
    for (int i = 0; i < 2; i++) {
        ln_kernel<false, true><<<NROWS, 256>>>(p_seqs, nullptr,
            ln_attn_g + i * HDIM, ln_attn_b + i * HDIM, p_Q, p_ah, p_al);
        add_kernel<<<2048, 256>>>((const float4*)p_seqs, (const float4*)p_time,
                                  p_bh, p_bl);
        gemm_mma<0><<<ggrid, 256, GEMM_SMEM>>>(p_ah, p_al,
            p_wh + (0 * 2 + i) * WSZ, p_wl + (0 * 2 + i) * WSZ,
            qb + i * HDIM, nullptr, p_q, nullptr, nullptr);
        gemm_mma<0><<<ggrid, 256, GEMM_SMEM>>>(p_th, p_tl,
            p_wh + (1 * 2 + i) * WSZ, p_wl + (1 * 2 + i) * WSZ,
            kb + i * HDIM, nullptr, p_k, nullptr, nullptr);
        gemm_mma<0><<<ggrid, 256, GEMM_SMEM>>>(p_bh, p_bl,
            p_wh + (2 * 2 + i) * WSZ, p_wl + (2 * 2 + i) * WSZ,
            vb + i * HDIM, nullptr, p_v, nullptr, nullptr);
        attn_kernel<<<dim3(4, 4, NBATCH), 256, ATTN_SMEM>>>(i);
        ln_kernel<true, true><<<NROWS, 256>>>(p_Q, p_ao,
            ln_ffn_g + i * HDIM, ln_ffn_b + i * HDIM, p_x, p_ah, p_al);
        gemm_mma<1><<<ggrid, 256, GEMM_SMEM>>>(p_ah, p_al,
            p_wh + (3 * 2 + i) * WSZ, p_wl + (3 * 2 + i) * WSZ,
            c1b + i * HDIM, nullptr, nullptr, p_bh, p_bl);
        gemm_mma<2><<<ggrid, 256, GEMM_SMEM>>>(p_bh, p_bl,
            p_wh + (4 * 2 + i) * WSZ, p_wl + (4 * 2 + i) * WSZ,
            c2b + i * HDIM, p_x, p_seqs, nullptr, nullptr);
    }
    ln_kernel<false, false><<<NROWS, 256>>>(p_seqs, nullptr, last_g, last_b,
                                            (float*)d_out, nullptr, nullptr);
}

// round 5
// speedup vs baseline: 2.7524x; 1.3240x over previous
#include <cuda_runtime.h>
#include <cuda_bf16.h>
#include <math.h>

#define NROWS 32768          // B*L
#define HDIM  256
#define LSEQ  512
#define NBATCH 64
#define HEADD 64
#define ITEMPAD 49999

typedef unsigned long long u64;

// ---------------- scratch (device globals; no allocs allowed) ----------------
__device__ __align__(16) float g_seqs[NROWS * HDIM];
__device__ __align__(16) float g_time[NROWS * HDIM];
__device__ __align__(16) float g_Q   [NROWS * HDIM];
__device__ __align__(16) float g_ao  [NROWS * HDIM];
__device__ __align__(16) float g_x   [NROWS * HDIM];
__device__ float g_keep[NROWS];
__device__ float g_gates[NROWS * 2];

// bf16 hi/lo split buffers
__device__ __align__(16) __nv_bfloat16 g_t_hi[NROWS * HDIM];
__device__ __align__(16) __nv_bfloat16 g_t_lo[NROWS * HDIM];
__device__ __align__(16) __nv_bfloat16 g_a_hi[NROWS * HDIM];   // bufA (LN out / ffn in)
__device__ __align__(16) __nv_bfloat16 g_a_lo[NROWS * HDIM];
__device__ __align__(16) __nv_bfloat16 g_b_hi[NROWS * HDIM];   // bufB (v in / ffn hidden)
__device__ __align__(16) __nv_bfloat16 g_b_lo[NROWS * HDIM];
__device__ __align__(16) __nv_bfloat16 g_qh[NROWS * HDIM];
__device__ __align__(16) __nv_bfloat16 g_ql[NROWS * HDIM];
__device__ __align__(16) __nv_bfloat16 g_kh[NROWS * HDIM];
__device__ __align__(16) __nv_bfloat16 g_kl[NROWS * HDIM];
__device__ __align__(16) __nv_bfloat16 g_vh[NROWS * HDIM];
__device__ __align__(16) __nv_bfloat16 g_vl[NROWS * HDIM];
// weights: [mat(q,k,v,c1,c2)][block][256][256]
__device__ __align__(16) __nv_bfloat16 g_w_hi[5 * 2 * HDIM * HDIM];
__device__ __align__(16) __nv_bfloat16 g_w_lo[5 * 2 * HDIM * HDIM];

// ---------------- small helpers ----------------------------------------------
__device__ __forceinline__ void split_bf(float x, __nv_bfloat16& h, __nv_bfloat16& l) {
    h = __float2bfloat16_rn(x);
    l = __float2bfloat16_rn(x - __bfloat162float(h));
}
__device__ __forceinline__ unsigned pack_bf2(__nv_bfloat16 a, __nv_bfloat16 b) {
    return (unsigned)__bfloat16_as_ushort(a) | ((unsigned)__bfloat16_as_ushort(b) << 16);
}
__device__ __forceinline__ unsigned smem_u32(const void* p) {
    unsigned a;
    asm("{ .reg .u64 t; cvta.to.shared.u64 t, %1; cvt.u32.u64 %0, t; }" : "=r"(a) : "l"(p));
    return a;
}

// ---------------- warp-MMA helpers (portable: sm_80+) -------------------------
__device__ __forceinline__ void ldsm_x4(unsigned& r0, unsigned& r1, unsigned& r2,
                                        unsigned& r3, unsigned addr) {
    asm volatile("ldmatrix.sync.aligned.m8n8.x4.shared.b16 {%0,%1,%2,%3}, [%4];"
        : "=r"(r0), "=r"(r1), "=r"(r2), "=r"(r3) : "r"(addr));
}
__device__ __forceinline__ void ldsm_x4_t(unsigned& r0, unsigned& r1, unsigned& r2,
                                          unsigned& r3, unsigned addr) {
    asm volatile("ldmatrix.sync.aligned.m8n8.x4.trans.shared.b16 {%0,%1,%2,%3}, [%4];"
        : "=r"(r0), "=r"(r1), "=r"(r2), "=r"(r3) : "r"(addr));
}
__device__ __forceinline__ void mma16816(float* d, const unsigned* a, const unsigned* b) {
    asm volatile("mma.sync.aligned.m16n8k16.row.col.f32.bf16.bf16.f32 "
        "{%0,%1,%2,%3}, {%4,%5,%6,%7}, {%8,%9}, {%0,%1,%2,%3};"
        : "+f"(d[0]), "+f"(d[1]), "+f"(d[2]), "+f"(d[3])
        : "r"(a[0]), "r"(a[1]), "r"(a[2]), "r"(a[3]), "r"(b[0]), "r"(b[1]));
}

// ---------------- prep: pe gather, seqs/time, keep, gates, time hi/lo --------
__global__ __launch_bounds__(256) void prep_kernel(
    const int* __restrict__ seqs_data, const float* __restrict__ seqs_in,
    const int* __restrict__ position, const float* __restrict__ time_in,
    const float* __restrict__ pos_table, const float* __restrict__ gate_W,
    const float* __restrict__ gate_b)
{
    const int n = blockIdx.x;
    const int h = threadIdx.x;
    const size_t idx = (size_t)n * HDIM + h;
    const int p = position[n];
    const float pe = pos_table[(size_t)p * HDIM + h];
    const float t = time_in[idx] + pe;
    const float keep = (seqs_data[n] != ITEMPAD) ? 1.f : 0.f;
    g_seqs[idx] = (seqs_in[idx] + pe) * keep;
    g_time[idx] = t;
    __nv_bfloat16 th, tl;
    split_bf(t, th, tl);
    g_t_hi[idx] = th; g_t_lo[idx] = tl;
    if (h == 0) g_keep[n] = keep;

    __shared__ float red[2][8];
    float p0 = t * gate_W[h];
    float p1 = t * gate_W[HDIM + h];
    #pragma unroll
    for (int o = 16; o; o >>= 1) {
        p0 += __shfl_xor_sync(0xffffffffu, p0, o);
        p1 += __shfl_xor_sync(0xffffffffu, p1, o);
    }
    if ((h & 31) == 0) { red[0][h >> 5] = p0; red[1][h >> 5] = p1; }
    __syncthreads();
    if (h < 2) {
        float s = 0.f;
        #pragma unroll
        for (int j = 0; j < 8; j++) s += red[h][j];
        g_gates[(size_t)n * 2 + h] = 1.f / (1.f + __expf(-(s + gate_b[h])));
    }
}

// ---------------- weight conversion ------------------------------------------
__global__ __launch_bounds__(256) void wconv_kernel(
    const float* __restrict__ q, const float* __restrict__ k,
    const float* __restrict__ v, const float* __restrict__ c1,
    const float* __restrict__ c2)
{
    const int i = blockIdx.x * blockDim.x + threadIdx.x;   // float4 units
    if (i >= 5 * 32768) return;
    const int mat = i >> 15, rem = i & 32767;
    const float* src = (mat == 0) ? q : (mat == 1) ? k : (mat == 2) ? v : (mat == 3) ? c1 : c2;
    float4 x = ((const float4*)src)[rem];
    __nv_bfloat16 h0,l0,h1,l1,h2,l2,h3,l3;
    split_bf(x.x,h0,l0); split_bf(x.y,h1,l1); split_bf(x.z,h2,l2); split_bf(x.w,h3,l3);
    const size_t o = ((size_t)mat << 17) + (size_t)rem * 4;
    *(uint2*)(g_w_hi + o) = make_uint2(pack_bf2(h0,h1), pack_bf2(h2,h3));
    *(uint2*)(g_w_lo + o) = make_uint2(pack_bf2(l0,l1), pack_bf2(l2,l3));
}

// ---------------- layernorm (+residual, +bf16 split outputs) ------------------
template<bool ADD, bool BF>
__global__ __launch_bounds__(256) void ln_kernel(
    const float* __restrict__ A, const float* __restrict__ B2,
    const float* __restrict__ g, const float* __restrict__ beta,
    float* __restrict__ dst, __nv_bfloat16* __restrict__ Dh,
    __nv_bfloat16* __restrict__ Dl)
{
    const int n = blockIdx.x;
    const int h = threadIdx.x;
    const size_t idx = (size_t)n * HDIM + h;
    float x = A[idx];
    if (ADD) x += B2[idx];
    float s = x, q = x * x;
    __shared__ float rs[8], rq[8];
    #pragma unroll
    for (int o = 16; o; o >>= 1) {
        s += __shfl_xor_sync(0xffffffffu, s, o);
        q += __shfl_xor_sync(0xffffffffu, q, o);
    }
    if ((h & 31) == 0) { rs[h >> 5] = s; rq[h >> 5] = q; }
    __syncthreads();
    float tot = 0.f, totq = 0.f;
    #pragma unroll
    for (int j = 0; j < 8; j++) { tot += rs[j]; totq += rq[j]; }
    const float mean = tot * (1.f / HDIM);
    const float var  = totq * (1.f / HDIM) - mean * mean;
    const float y = (x - mean) * rsqrtf(var + 1e-8f) * g[h] + beta[h];
    dst[idx] = y;
    if (BF) {
        __nv_bfloat16 hh, ll;
        split_bf(y, hh, ll);
        Dh[idx] = hh; Dl[idx] = ll;
    }
}

// ---------------- add (seqs+time) -> bf16 hi/lo -------------------------------
__global__ __launch_bounds__(256) void add_kernel(
    const float4* __restrict__ a, const float4* __restrict__ b,
    __nv_bfloat16* __restrict__ Ch, __nv_bfloat16* __restrict__ Cl)
{
    const int total = NROWS * HDIM / 4;
    for (int i = blockIdx.x * blockDim.x + threadIdx.x; i < total;
         i += gridDim.x * blockDim.x) {
        float4 x = a[i], y = b[i];
        float s0 = x.x + y.x, s1 = x.y + y.y, s2 = x.z + y.z, s3 = x.w + y.w;
        __nv_bfloat16 h0,l0,h1,l1,h2,l2,h3,l3;
        split_bf(s0,h0,l0); split_bf(s1,h1,l1); split_bf(s2,h2,l2); split_bf(s3,h3,l3);
        *(uint2*)(Ch + (size_t)i * 4) = make_uint2(pack_bf2(h0,h1), pack_bf2(h2,h3));
        *(uint2*)(Cl + (size_t)i * 4) = make_uint2(pack_bf2(l0,l1), pack_bf2(l2,l3));
    }
}

// ---------------- warp-MMA GEMM: C[128,64-tile] = A @ W^T + bias --------------
// EPI: 0 = fp32 out, 1 = relu -> bf16 hi/lo, 2 = (+R)*keep -> fp32, 3 = bf16 hi/lo
#define ASTRIDE 72
#define SM_AH 0
#define SM_AL (128 * ASTRIDE)
#define SM_BH (2 * 128 * ASTRIDE)
#define SM_BL (2 * 128 * ASTRIDE + 64 * ASTRIDE)
#define GEMM_SMEM ((2 * 128 * ASTRIDE + 2 * 64 * ASTRIDE) * 2)

template<int EPI>
__global__ __launch_bounds__(256, 2) void gemm_mma(
    const __nv_bfloat16* __restrict__ Ah, const __nv_bfloat16* __restrict__ Al,
    const __nv_bfloat16* __restrict__ Wh, const __nv_bfloat16* __restrict__ Wl,
    const float* __restrict__ bias, const float* __restrict__ R,
    float* __restrict__ Cf, __nv_bfloat16* __restrict__ Ch,
    __nv_bfloat16* __restrict__ Cl)
{
    extern __shared__ __align__(16) __nv_bfloat16 smb[];
    const int tid = threadIdx.x;
    const int lane = tid & 31, wid = tid >> 5;
    const int bm = blockIdx.x << 7;
    const int bn = blockIdx.y << 6;
    const int wm = (wid >> 1) << 5;
    const int wn = (wid & 1) << 5;

    float acc[2][4][4];
    #pragma unroll
    for (int mt = 0; mt < 2; mt++)
        #pragma unroll
        for (int nt = 0; nt < 4; nt++)
            #pragma unroll
            for (int j = 0; j < 4; j++) acc[mt][nt][j] = 0.f;

    const unsigned sbase = smem_u32(smb);
    const int a_r = ((lane >> 3) & 1) * 8 + (lane & 7);
    const int a_c = (lane >> 4) * 8;
    const int b_r = (lane >> 4) * 8 + (lane & 7);
    const int b_c = ((lane >> 3) & 1) * 8;

    for (int c = 0; c < 4; c++) {
        #pragma unroll
        for (int i = 0; i < 4; i++) {
            const int v = tid + 256 * i;
            const int r = v >> 3, cc = v & 7;
            const size_t go = (size_t)(bm + r) * HDIM + c * 64 + cc * 8;
            const int so = r * ASTRIDE + cc * 8;
            *(uint4*)(smb + SM_AH + so) = *(const uint4*)(Ah + go);
            *(uint4*)(smb + SM_AL + so) = *(const uint4*)(Al + go);
        }
        #pragma unroll
        for (int i = 0; i < 2; i++) {
            const int v = tid + 256 * i;
            const int r = v >> 3, cc = v & 7;
            const size_t go = (size_t)(bn + r) * HDIM + c * 64 + cc * 8;
            const int so = r * ASTRIDE + cc * 8;
            *(uint4*)(smb + SM_BH + so) = *(const uint4*)(Wh + go);
            *(uint4*)(smb + SM_BL + so) = *(const uint4*)(Wl + go);
        }
        __syncthreads();

        #pragma unroll
        for (int ks = 0; ks < 4; ks++) {
            const int k = ks * 16;
            unsigned ah[2][4], al[2][4], bh[4][2], bl[4][2];
            #pragma unroll
            for (int mt = 0; mt < 2; mt++) {
                const unsigned off =
                    ((unsigned)((wm + mt * 16 + a_r) * ASTRIDE + k + a_c)) * 2u;
                ldsm_x4(ah[mt][0], ah[mt][1], ah[mt][2], ah[mt][3],
                        sbase + SM_AH * 2 + off);
                ldsm_x4(al[mt][0], al[mt][1], al[mt][2], al[mt][3],
                        sbase + SM_AL * 2 + off);
            }
            #pragma unroll
            for (int nt2 = 0; nt2 < 2; nt2++) {
                const unsigned off =
                    ((unsigned)((wn + nt2 * 16 + b_r) * ASTRIDE + k + b_c)) * 2u;
                unsigned r0, r1, r2, r3;
                ldsm_x4(r0, r1, r2, r3, sbase + SM_BH * 2 + off);
                bh[nt2 * 2][0] = r0; bh[nt2 * 2][1] = r1;
                bh[nt2 * 2 + 1][0] = r2; bh[nt2 * 2 + 1][1] = r3;
                ldsm_x4(r0, r1, r2, r3, sbase + SM_BL * 2 + off);
                bl[nt2 * 2][0] = r0; bl[nt2 * 2][1] = r1;
                bl[nt2 * 2 + 1][0] = r2; bl[nt2 * 2 + 1][1] = r3;
            }
            #pragma unroll
            for (int mt = 0; mt < 2; mt++)
                #pragma unroll
                for (int nt = 0; nt < 4; nt++) {
                    mma16816(acc[mt][nt], ah[mt], bh[nt]);
                    mma16816(acc[mt][nt], al[mt], bh[nt]);
                    mma16816(acc[mt][nt], ah[mt], bl[nt]);
                }
        }
        __syncthreads();
    }

    const int qrow = lane >> 2;
    const int qcol = (lane & 3) * 2;
    #pragma unroll
    for (int mt = 0; mt < 2; mt++) {
        #pragma unroll
        for (int half = 0; half < 2; half++) {
            const int row = bm + wm + mt * 16 + qrow + half * 8;
            float keep = 1.f;
            if (EPI == 2) keep = g_keep[row];
            #pragma unroll
            for (int nt = 0; nt < 4; nt++) {
                const int col = bn + wn + nt * 8 + qcol;
                float v0 = acc[mt][nt][half * 2]     + __ldg(bias + col);
                float v1 = acc[mt][nt][half * 2 + 1] + __ldg(bias + col + 1);
                const size_t o = (size_t)row * HDIM + col;
                if (EPI == 0) {
                    *(float2*)(Cf + o) = make_float2(v0, v1);
                } else if (EPI == 1 || EPI == 3) {
                    if (EPI == 1) { v0 = fmaxf(v0, 0.f); v1 = fmaxf(v1, 0.f); }
                    __nv_bfloat16 h0, l0, h1, l1;
                    split_bf(v0, h0, l0); split_bf(v1, h1, l1);
                    *(unsigned*)(Ch + o) = pack_bf2(h0, h1);
                    *(unsigned*)(Cl + o) = pack_bf2(l0, l1);
                } else {
                    const float2 rr = *(const float2*)(R + o);
                    *(float2*)(Cf + o) = make_float2((v0 + rr.x) * keep,
                                                     (v1 + rr.y) * keep);
                }
            }
        }
    }
}

// ---------------- flash attention (MMA, causal, gated) ------------------------
// grid (4, 4, 64), 256 threads = 8 warps; warp w owns q rows [q0+16w, q0+16w+16).
#define AT_AST 72
#define SQH_B 0
#define SQL_B (128 * AT_AST * 2)
#define SKH_B (2 * 128 * AT_AST * 2)
#define SKL_B (SKH_B + 64 * AT_AST * 2)
#define SVH_B (SKL_B + 64 * AT_AST * 2)
#define SVL_B (SVH_B + 64 * AT_AST * 2)
#define STG_B (SVL_B + 64 * AT_AST * 2)
#define ATTN_SMEM (STG_B + 64 * 4)

__global__ __launch_bounds__(256) void attn_kernel(int blk)
{
    extern __shared__ __align__(16) __nv_bfloat16 smb[];
    float* stgk = (float*)((char*)smb + STG_B);

    const int tid = threadIdx.x;
    const int lane = tid & 31, wid = tid >> 5;
    const int qt = blockIdx.x, hh = blockIdx.y, b = blockIdx.z;
    const int q0 = qt * 128;
    const size_t base = (size_t)b * LSEQ;
    const int wm = wid * 16;
    const unsigned sbase = smem_u32(smb);

    // stage Q (hi/lo) into smem
    #pragma unroll
    for (int i = 0; i < 4; i++) {
        const int v = tid + 256 * i;
        const int r = v >> 3, cc = v & 7;
        const size_t go = (base + q0 + r) * HDIM + hh * HEADD + cc * 8;
        *(uint4*)((char*)smb + SQH_B + (r * AT_AST + cc * 8) * 2) = *(const uint4*)(g_qh + go);
        *(uint4*)((char*)smb + SQL_B + (r * AT_AST + cc * 8) * 2) = *(const uint4*)(g_ql + go);
    }
    __syncthreads();

    const int a_r = ((lane >> 3) & 1) * 8 + (lane & 7);
    const int a_c = (lane >> 4) * 8;
    const int b_r = (lane >> 4) * 8 + (lane & 7);
    const int b_c = ((lane >> 3) & 1) * 8;
    const int v_r = lane & 15;
    const int v_c = (lane >> 4) * 8;

    unsigned aqh[4][4], aql[4][4];
    #pragma unroll
    for (int ks = 0; ks < 4; ks++) {
        const unsigned off = ((unsigned)((wm + a_r) * AT_AST + ks * 16 + a_c)) * 2u;
        ldsm_x4(aqh[ks][0], aqh[ks][1], aqh[ks][2], aqh[ks][3], sbase + SQH_B + off);
        ldsm_x4(aql[ks][0], aql[ks][1], aql[ks][2], aql[ks][3], sbase + SQL_B + off);
    }

    const int r = lane >> 2;
    const int c2 = (lane & 3) * 2;
    const float cq0 = 0.125f * g_gates[(base + q0 + wm + r) * 2 + blk];
    const float cq1 = 0.125f * g_gates[(base + q0 + wm + r + 8) * 2 + blk];
    float mrow0 = -1e30f, mrow1 = -1e30f, lrow0 = 0.f, lrow1 = 0.f;
    float O[8][4];
    #pragma unroll
    for (int nt = 0; nt < 8; nt++)
        #pragma unroll
        for (int j = 0; j < 4; j++) O[nt][j] = 0.f;

    const int nkt = 2 * (qt + 1);
    for (int kt = 0; kt < nkt; kt++) {
        const int k0 = kt * 64;
        __syncthreads();   // previous tile fully consumed before overwrite
        #pragma unroll
        for (int i = 0; i < 2; i++) {
            const int v = tid + 256 * i;
            const int rr = v >> 3, cc = v & 7;
            const size_t go = (base + k0 + rr) * HDIM + hh * HEADD + cc * 8;
            const int so = (rr * AT_AST + cc * 8) * 2;
            *(uint4*)((char*)smb + SKH_B + so) = *(const uint4*)(g_kh + go);
            *(uint4*)((char*)smb + SKL_B + so) = *(const uint4*)(g_kl + go);
            *(uint4*)((char*)smb + SVH_B + so) = *(const uint4*)(g_vh + go);
            *(uint4*)((char*)smb + SVL_B + so) = *(const uint4*)(g_vl + go);
        }
        if (tid < 64) stgk[tid] = g_gates[(base + k0 + tid) * 2 + blk];
        __syncthreads();

        // ---- S = Q K^T ----
        float S[8][4];
        #pragma unroll
        for (int nt = 0; nt < 8; nt++)
            #pragma unroll
            for (int j = 0; j < 4; j++) S[nt][j] = 0.f;
        #pragma unroll
        for (int ks = 0; ks < 4; ks++) {
            #pragma unroll
            for (int n16 = 0; n16 < 4; n16++) {
                const unsigned off =
                    ((unsigned)((n16 * 16 + b_r) * AT_AST + ks * 16 + b_c)) * 2u;
                unsigned h0, h1, h2, h3, l0, l1, l2, l3;
                ldsm_x4(h0, h1, h2, h3, sbase + SKH_B + off);
                ldsm_x4(l0, l1, l2, l3, sbase + SKL_B + off);
                unsigned bh0[2] = {h0, h1}, bh1[2] = {h2, h3};
                unsigned bl0[2] = {l0, l1}, bl1[2] = {l2, l3};
                mma16816(S[2 * n16], aqh[ks], bh0);
                mma16816(S[2 * n16], aql[ks], bh0);
                mma16816(S[2 * n16], aqh[ks], bl0);
                mma16816(S[2 * n16 + 1], aqh[ks], bh1);
                mma16816(S[2 * n16 + 1], aql[ks], bh1);
                mma16816(S[2 * n16 + 1], aqh[ks], bl1);
            }
        }

        // ---- gate, mask, softmax ----
        const bool need_mask = (k0 + 63 > q0 + wm);
        float mt0 = -1e30f, mt1 = -1e30f;
        #pragma unroll
        for (int nt = 0; nt < 8; nt++) {
            const int col = nt * 8 + c2;
            const float tga = stgk[col], tgb = stgk[col + 1];
            float v0 = S[nt][0] * cq0 * tga;
            float v1 = S[nt][1] * cq0 * tgb;
            float v2 = S[nt][2] * cq1 * tga;
            float v3 = S[nt][3] * cq1 * tgb;
            if (need_mask) {
                const int kg = k0 + col;
                const int qa = q0 + wm + r, qb2 = qa + 8;
                if (kg     > qa)  v0 = -1e30f;
                if (kg + 1 > qa)  v1 = -1e30f;
                if (kg     > qb2) v2 = -1e30f;
                if (kg + 1 > qb2) v3 = -1e30f;
            }
            S[nt][0] = v0; S[nt][1] = v1; S[nt][2] = v2; S[nt][3] = v3;
            mt0 = fmaxf(mt0, fmaxf(v0, v1));
            mt1 = fmaxf(mt1, fmaxf(v2, v3));
        }
        mt0 = fmaxf(mt0, __shfl_xor_sync(0xffffffffu, mt0, 1));
        mt0 = fmaxf(mt0, __shfl_xor_sync(0xffffffffu, mt0, 2));
        mt1 = fmaxf(mt1, __shfl_xor_sync(0xffffffffu, mt1, 1));
        mt1 = fmaxf(mt1, __shfl_xor_sync(0xffffffffu, mt1, 2));
        const float mn0 = fmaxf(mrow0, mt0), mn1 = fmaxf(mrow1, mt1);
        const float al0 = __expf(mrow0 - mn0), al1 = __expf(mrow1 - mn1);
        mrow0 = mn0; mrow1 = mn1;

        float rs0 = 0.f, rs1 = 0.f;
        unsigned pah[4][4], pal[4][4];
        #pragma unroll
        for (int j2 = 0; j2 < 4; j2++) {
            float p0 = __expf(S[2 * j2][0] - mn0);
            float p1 = __expf(S[2 * j2][1] - mn0);
            float p2 = __expf(S[2 * j2][2] - mn1);
            float p3 = __expf(S[2 * j2][3] - mn1);
            float p4 = __expf(S[2 * j2 + 1][0] - mn0);
            float p5 = __expf(S[2 * j2 + 1][1] - mn0);
            float p6 = __expf(S[2 * j2 + 1][2] - mn1);
            float p7 = __expf(S[2 * j2 + 1][3] - mn1);
            rs0 += (p0 + p1) + (p4 + p5);
            rs1 += (p2 + p3) + (p6 + p7);
            __nv_bfloat16 h0,l0,h1,l1,h2,l2,h3,l3,h4,l4,h5,l5,h6,l6,h7,l7;
            split_bf(p0,h0,l0); split_bf(p1,h1,l1); split_bf(p2,h2,l2); split_bf(p3,h3,l3);
            split_bf(p4,h4,l4); split_bf(p5,h5,l5); split_bf(p6,h6,l6); split_bf(p7,h7,l7);
            pah[j2][0] = pack_bf2(h0, h1); pal[j2][0] = pack_bf2(l0, l1);
            pah[j2][1] = pack_bf2(h2, h3); pal[j2][1] = pack_bf2(l2, l3);
            pah[j2][2] = pack_bf2(h4, h5); pal[j2][2] = pack_bf2(l4, l5);
            pah[j2][3] = pack_bf2(h6, h7); pal[j2][3] = pack_bf2(l6, l7);
        }
        rs0 += __shfl_xor_sync(0xffffffffu, rs0, 1);
        rs0 += __shfl_xor_sync(0xffffffffu, rs0, 2);
        rs1 += __shfl_xor_sync(0xffffffffu, rs1, 1);
        rs1 += __shfl_xor_sync(0xffffffffu, rs1, 2);
        lrow0 = lrow0 * al0 + rs0;
        lrow1 = lrow1 * al1 + rs1;

        #pragma unroll
        for (int nt = 0; nt < 8; nt++) {
            O[nt][0] *= al0; O[nt][1] *= al0;
            O[nt][2] *= al1; O[nt][3] *= al1;
        }

        // ---- O += P V ----
        #pragma unroll
        for (int ks = 0; ks < 4; ks++) {
            #pragma unroll
            for (int n16 = 0; n16 < 4; n16++) {
                const unsigned off =
                    ((unsigned)((ks * 16 + v_r) * AT_AST + n16 * 16 + v_c)) * 2u;
                unsigned h0, h1, h2, h3, l0, l1, l2, l3;
                ldsm_x4_t(h0, h1, h2, h3, sbase + SVH_B + off);
                ldsm_x4_t(l0, l1, l2, l3, sbase + SVL_B + off);
                unsigned bh0[2] = {h0, h1}, bh1[2] = {h2, h3};
                unsigned bl0[2] = {l0, l1}, bl1[2] = {l2, l3};
                mma16816(O[2 * n16], pah[ks], bh0);
                mma16816(O[2 * n16], pal[ks], bh0);
                mma16816(O[2 * n16], pah[ks], bl0);
                mma16816(O[2 * n16 + 1], pah[ks], bh1);
                mma16816(O[2 * n16 + 1], pal[ks], bh1);
                mma16816(O[2 * n16 + 1], pah[ks], bl1);
            }
        }
    }

    // ---- normalize + store ----
    const float inv0 = 1.f / lrow0, inv1 = 1.f / lrow1;
    const size_t row0 = (base + q0 + wm + r) * HDIM + hh * HEADD;
    const size_t row1 = (base + q0 + wm + r + 8) * HDIM + hh * HEADD;
    #pragma unroll
    for (int nt = 0; nt < 8; nt++) {
        const int col = nt * 8 + c2;
        *(float2*)(g_ao + row0 + col) = make_float2(O[nt][0] * inv0, O[nt][1] * inv0);
        *(float2*)(g_ao + row1 + col) = make_float2(O[nt][2] * inv1, O[nt][3] * inv1);
    }
}

// ---------------- launcher ---------------------------------------------------
extern "C" void kernel_launch(void* const* d_in, const int* in_sizes, int n_in,
                              void* d_out, int out_size)
{
    const int*   seqs_data = (const int*)  d_in[0];
    const float* seqs_in   = (const float*)d_in[1];
    const int*   position  = (const int*)  d_in[2];
    const float* time_in   = (const float*)d_in[3];
    const float* pos_table = (const float*)d_in[4];
    const float* gate_W    = (const float*)d_in[5];
    const float* gate_b    = (const float*)d_in[6];
    const float* ln_attn_g = (const float*)d_in[7];
    const float* ln_attn_b = (const float*)d_in[8];
    const float* qW        = (const float*)d_in[9];
    const float* qb        = (const float*)d_in[10];
    const float* kW        = (const float*)d_in[11];
    const float* kb        = (const float*)d_in[12];
    const float* vW        = (const float*)d_in[13];
    const float* vb        = (const float*)d_in[14];
    const float* ln_ffn_g  = (const float*)d_in[15];
    const float* ln_ffn_b  = (const float*)d_in[16];
    const float* c1W       = (const float*)d_in[17];
    const float* c1b       = (const float*)d_in[18];
    const float* c2W       = (const float*)d_in[19];
    const float* c2b       = (const float*)d_in[20];
    const float* last_g    = (const float*)d_in[21];
    const float* last_b    = (const float*)d_in[22];

    float *p_seqs, *p_time, *p_Q, *p_ao, *p_x;
    __nv_bfloat16 *p_th, *p_tl, *p_ah, *p_al, *p_bh, *p_bl, *p_wh, *p_wl;
    __nv_bfloat16 *p_qh, *p_ql, *p_kh, *p_kl, *p_vh, *p_vl;
    cudaGetSymbolAddress((void**)&p_seqs, g_seqs);
    cudaGetSymbolAddress((void**)&p_time, g_time);
    cudaGetSymbolAddress((void**)&p_Q,    g_Q);
    cudaGetSymbolAddress((void**)&p_ao,   g_ao);
    cudaGetSymbolAddress((void**)&p_x,    g_x);
    cudaGetSymbolAddress((void**)&p_th,   g_t_hi);
    cudaGetSymbolAddress((void**)&p_tl,   g_t_lo);
    cudaGetSymbolAddress((void**)&p_ah,   g_a_hi);
    cudaGetSymbolAddress((void**)&p_al,   g_a_lo);
    cudaGetSymbolAddress((void**)&p_bh,   g_b_hi);
    cudaGetSymbolAddress((void**)&p_bl,   g_b_lo);
    cudaGetSymbolAddress((void**)&p_wh,   g_w_hi);
    cudaGetSymbolAddress((void**)&p_wl,   g_w_lo);
    cudaGetSymbolAddress((void**)&p_qh,   g_qh);
    cudaGetSymbolAddress((void**)&p_ql,   g_ql);
    cudaGetSymbolAddress((void**)&p_kh,   g_kh);
    cudaGetSymbolAddress((void**)&p_kl,   g_kl);
    cudaGetSymbolAddress((void**)&p_vh,   g_vh);
    cudaGetSymbolAddress((void**)&p_vl,   g_vl);

    cudaFuncSetAttribute(attn_kernel, cudaFuncAttributeMaxDynamicSharedMemorySize, ATTN_SMEM);
    cudaFuncSetAttribute(gemm_mma<0>, cudaFuncAttributeMaxDynamicSharedMemorySize, GEMM_SMEM);
    cudaFuncSetAttribute(gemm_mma<1>, cudaFuncAttributeMaxDynamicSharedMemorySize, GEMM_SMEM);
    cudaFuncSetAttribute(gemm_mma<2>, cudaFuncAttributeMaxDynamicSharedMemorySize, GEMM_SMEM);
    cudaFuncSetAttribute(gemm_mma<3>, cudaFuncAttributeMaxDynamicSharedMemorySize, GEMM_SMEM);

    prep_kernel<<<NROWS, 256>>>(seqs_data, seqs_in, position, time_in,
                                pos_table, gate_W, gate_b);
    wconv_kernel<<<640, 256>>>(qW, kW, vW, c1W, c2W);

    const size_t WSZ = (size_t)HDIM * HDIM;
    const dim3 ggrid(NROWS / 128, HDIM / 64);
    for (int i = 0; i < 2; i++) {
        ln_kernel<false, true><<<NROWS, 256>>>(p_seqs, nullptr,
            ln_attn_g + i * HDIM, ln_attn_b + i * HDIM, p_Q, p_ah, p_al);
        add_kernel<<<2048, 256>>>((const float4*)p_seqs, (const float4*)p_time,
                                  p_bh, p_bl);
        gemm_mma<3><<<ggrid, 256, GEMM_SMEM>>>(p_ah, p_al,
            p_wh + (0 * 2 + i) * WSZ, p_wl + (0 * 2 + i) * WSZ,
            qb + i * HDIM, nullptr, nullptr, p_qh, p_ql);
        gemm_mma<3><<<ggrid, 256, GEMM_SMEM>>>(p_th, p_tl,
            p_wh + (1 * 2 + i) * WSZ, p_wl + (1 * 2 + i) * WSZ,
            kb + i * HDIM, nullptr, nullptr, p_kh, p_kl);
        gemm_mma<3><<<ggrid, 256, GEMM_SMEM>>>(p_bh, p_bl,
            p_wh + (2 * 2 + i) * WSZ, p_wl + (2 * 2 + i) * WSZ,
            vb + i * HDIM, nullptr, nullptr, p_vh, p_vl);
        attn_kernel<<<dim3(4, 4, NBATCH), 256, ATTN_SMEM>>>(i);
        ln_kernel<true, true><<<NROWS, 256>>>(p_Q, p_ao,
            ln_ffn_g + i * HDIM, ln_ffn_b + i * HDIM, p_x, p_ah, p_al);
        gemm_mma<1><<<ggrid, 256, GEMM_SMEM>>>(p_ah, p_al,
            p_wh + (3 * 2 + i) * WSZ, p_wl + (3 * 2 + i) * WSZ,
            c1b + i * HDIM, nullptr, nullptr, p_bh, p_bl);
        gemm_mma<2><<<ggrid, 256, GEMM_SMEM>>>(p_bh, p_bl,
            p_wh + (4 * 2 + i) * WSZ, p_wl + (4 * 2 + i) * WSZ,
            c2b + i * HDIM, p_x, p_seqs, nullptr, nullptr);
    }
    ln_kernel<false, false><<<NROWS, 256>>>(p_seqs, nullptr, last_g, last_b,
                                            (float*)d_out, nullptr, nullptr);
}